// round 11
// baseline (speedup 1.0000x reference)
#include <cuda_runtime.h>
#include <cuda_bf16.h>
#include <math.h>
#include <stdint.h>

#define BATCH 4
#define SEQ   2048
#define DIM   1024
#define NCHUNK 16
#define CHUNK  128          // SEQ / NCHUNK
#define MROWS  (BATCH * SEQ)   // 8192

// ---------------- scratch (static device globals; no allocation) ----------------
__device__ float g_ret  [(size_t)MROWS * DIM];
__device__ float g_inp  [(size_t)MROWS * DIM];
__device__ float g_gate [(size_t)MROWS * DIM];
__device__ float g_u    [(size_t)MROWS * DIM];
__device__ float g_p    [(size_t)MROWS * DIM];
__device__ float g_state[(size_t)MROWS * DIM];
__device__ float g_y    [(size_t)MROWS * DIM];   // y_t = gate_{t+1} * state_t

#define REC_CTAS 128
#define REC_COLS 8
#define FLAG_STRIDE 8
__device__ unsigned int g_flags[REC_CTAS * FLAG_STRIDE];

__device__ float g_E   [BATCH * NCHUNK * DIM];
__device__ float g_cin [BATCH * NCHUNK * DIM];

// ---------------- helpers ----------------
__device__ __forceinline__ uint32_t smem_u32(const void* p) {
    uint32_t a;
    asm("{ .reg .u64 t; cvta.to.shared.u64 t, %1; cvt.u32.u64 %0, t; }"
        : "=r"(a) : "l"(p));
    return a;
}
__device__ __forceinline__ void ldm4(uint32_t* r, uint32_t addr) {
    asm volatile("ldmatrix.sync.aligned.m8n8.x4.shared.b16 {%0,%1,%2,%3}, [%4];"
                 : "=r"(r[0]), "=r"(r[1]), "=r"(r[2]), "=r"(r[3]) : "r"(addr));
}
__device__ __forceinline__ void mma16816(float* d, const uint32_t* a, const uint32_t* b) {
    asm volatile("mma.sync.aligned.m16n8k16.row.col.f32.bf16.bf16.f32 "
                 "{%0,%1,%2,%3}, {%4,%5,%6,%7}, {%8,%9}, {%0,%1,%2,%3};"
                 : "+f"(d[0]), "+f"(d[1]), "+f"(d[2]), "+f"(d[3])
                 : "r"(a[0]), "r"(a[1]), "r"(a[2]), "r"(a[3]),
                   "r"(b[0]), "r"(b[1]));
}

// ---------------- retention scan ----------------
__global__ void scan_pass1(const float* __restrict__ K, const float* __restrict__ V,
                           const float* __restrict__ decay)
{
    int d = blockIdx.x * 256 + threadIdx.x;
    int c = blockIdx.y;
    int b = blockIdx.z;
    float dec = decay[d >> 6];
    size_t base = ((size_t)b * SEQ + (size_t)c * CHUNK) * DIM + d;
    const float* kp = K + base;
    const float* vp = V + base;
    float r = 0.f;
#pragma unroll 8
    for (int i = 0; i < CHUNK; ++i)
        r = dec * r + kp[(size_t)i * DIM] * vp[(size_t)i * DIM];
    g_E[((size_t)b * NCHUNK + c) * DIM + d] = r;
}

__global__ void scan_pass2(const float* __restrict__ decay)
{
    int d = blockIdx.x * 256 + threadIdx.x;
    int b = blockIdx.y;
    float dec = decay[d >> 6];
    float decC = 1.f;
#pragma unroll
    for (int i = 0; i < CHUNK; ++i) decC *= dec;
    float carry = 0.f;
#pragma unroll
    for (int c = 0; c < NCHUNK; ++c) {
        size_t idx = ((size_t)b * NCHUNK + c) * DIM + d;
        g_cin[idx] = carry;
        carry = carry * decC + g_E[idx];
    }
}

__global__ void scan_pass3(const float* __restrict__ Q, const float* __restrict__ K,
                           const float* __restrict__ V, const float* __restrict__ decay)
{
    int d = blockIdx.x * 256 + threadIdx.x;
    int c = blockIdx.y;
    int b = blockIdx.z;
    float dec = decay[d >> 6];
    size_t base = ((size_t)b * SEQ + (size_t)c * CHUNK) * DIM + d;
    const float* qp = Q + base;
    const float* kp = K + base;
    const float* vp = V + base;
    float* rp = g_ret + base;
    float r = g_cin[((size_t)b * NCHUNK + c) * DIM + d];
#pragma unroll 8
    for (int i = 0; i < CHUNK; ++i) {
        r = dec * r + kp[(size_t)i * DIM] * vp[(size_t)i * DIM];
        rp[(size_t)i * DIM] = qp[(size_t)i * DIM] * r;
    }
}

// ================= pipelined mma.sync split-bf16 GEMM (round-10 winner, frozen) =================
#define GM_LDS    40                        // padded row elements: 80B stride
#define GM_TILE_B (128 * GM_LDS * 2)        // 10240 B per (tile,part)
#define GM_BUF_B  (4 * GM_TILE_B)           // Ahi|Alo|Bhi|Blo = 40960 B
#define GM_SMEM   (2 * GM_BUF_B)            // 81920 B

__device__ __forceinline__ void ld_cvt(uint32_t* r, const float* __restrict__ src,
                                       int rowBase, int kBase, int tid)
{
    const int row = tid >> 1;
    const int cb  = (tid & 1) * 16;
    const float4* sp = (const float4*)(src + (size_t)(rowBase + row) * DIM + kBase + cb);
#pragma unroll
    for (int j = 0; j < 4; ++j) {
        float4 v = sp[j];
        uint32_t u0 = __float_as_uint(v.x), u1 = __float_as_uint(v.y);
        uint32_t u2 = __float_as_uint(v.z), u3 = __float_as_uint(v.w);
        r[j*4+0] = (u0 >> 16) | (u1 & 0xFFFF0000u);
        r[j*4+1] = (u2 >> 16) | (u3 & 0xFFFF0000u);
        float l0 = v.x - __uint_as_float(u0 & 0xFFFF0000u);
        float l1 = v.y - __uint_as_float(u1 & 0xFFFF0000u);
        float l2 = v.z - __uint_as_float(u2 & 0xFFFF0000u);
        float l3 = v.w - __uint_as_float(u3 & 0xFFFF0000u);
        asm("cvt.rn.satfinite.bf16x2.f32 %0, %1, %2;" : "=r"(r[j*4+2]) : "f"(l1), "f"(l0));
        asm("cvt.rn.satfinite.bf16x2.f32 %0, %1, %2;" : "=r"(r[j*4+3]) : "f"(l3), "f"(l2));
    }
}

__device__ __forceinline__ void sts_tile(char* hiT, char* loT, const uint32_t* r, int tid)
{
    const int row = tid >> 1;
    const int cb  = (tid & 1) * 16;
#pragma unroll
    for (int j = 0; j < 4; ++j) {
        int bo = 2 * (row * GM_LDS + cb + j * 4);
        *(uint32_t*)(hiT + bo)     = r[j*4+0];
        *(uint32_t*)(hiT + bo + 4) = r[j*4+1];
        *(uint32_t*)(loT + bo)     = r[j*4+2];
        *(uint32_t*)(loT + bo + 4) = r[j*4+3];
    }
}

__global__ __launch_bounds__(256)
void mma_gemm(const float* __restrict__ X1, const float* __restrict__ W1,
              const float* __restrict__ X2, const float* __restrict__ W2,
              const float* __restrict__ bias, float* __restrict__ C,
              const float* __restrict__ auxIn, float* __restrict__ auxOut,
              int mode, int dual)
{
    extern __shared__ char dyn[];
    const uint32_t sb = smem_u32(dyn);
    const int tid = threadIdx.x;
    const int wid = tid >> 5, lane = tid & 31;
    const int wm = wid >> 1;
    const int wn = wid & 1;
    const int nTile = blockIdx.x * 128;
    const int mTile = blockIdx.y * 128;

    float acc[2][8][4];
#pragma unroll
    for (int mt = 0; mt < 2; ++mt)
#pragma unroll
        for (int nt = 0; nt < 8; ++nt)
#pragma unroll
            for (int r = 0; r < 4; ++r) acc[mt][nt][r] = 0.f;

    const uint32_t aRow  = wm * 32 + (lane & 15);
    const uint32_t aKoff = (lane >> 4) * 8;
    const uint32_t bRow  = wn * 64 + (lane & 7) + ((lane >> 4) << 3);
    const uint32_t bKoff = ((lane >> 3) & 1) * 8;

    uint32_t rA[16], rB[16];

    ld_cvt(rA, X1, mTile, 0, tid);
    ld_cvt(rB, W1, nTile, 0, tid);
    sts_tile(dyn, dyn + GM_TILE_B, rA, tid);
    sts_tile(dyn + 2 * GM_TILE_B, dyn + 3 * GM_TILE_B, rB, tid);
    __syncthreads();

    const int nCh = dual ? 64 : 32;
    for (int c = 0; c < nCh; ++c) {
        const int buf = c & 1;

        if (c + 1 < nCh) {
            const int c1 = c + 1;
            const float* X = (c1 >= 32) ? X2 : X1;
            const float* W = (c1 >= 32) ? W2 : W1;
            const int kB = (c1 & 31) * 32;
            ld_cvt(rA, X, mTile, kB, tid);
            ld_cvt(rB, W, nTile, kB, tid);
            char* nb = dyn + (buf ^ 1) * GM_BUF_B;
            sts_tile(nb, nb + GM_TILE_B, rA, tid);
            sts_tile(nb + 2 * GM_TILE_B, nb + 3 * GM_TILE_B, rB, tid);
        }

        const uint32_t base = sb + buf * GM_BUF_B;
#pragma unroll
        for (int kk = 0; kk < 2; ++kk) {
            uint32_t ahi[2][4], alo[2][4];
#pragma unroll
            for (int mt = 0; mt < 2; ++mt) {
                uint32_t off = 2u * ((aRow + mt * 16) * GM_LDS + kk * 16 + aKoff);
                ldm4(ahi[mt], base + off);
                ldm4(alo[mt], base + GM_TILE_B + off);
            }
#pragma unroll
            for (int ng = 0; ng < 4; ++ng) {
                uint32_t bhi[4], blo[4];
                uint32_t off = 2u * ((bRow + ng * 16) * GM_LDS + kk * 16 + bKoff);
                ldm4(bhi, base + 2 * GM_TILE_B + off);
                ldm4(blo, base + 3 * GM_TILE_B + off);
#pragma unroll
                for (int mt = 0; mt < 2; ++mt)
#pragma unroll
                    for (int h = 0; h < 2; ++h) {
                        float* d = acc[mt][ng * 2 + h];
                        mma16816(d, ahi[mt], bhi + h * 2);
                        mma16816(d, ahi[mt], blo + h * 2);
                        mma16816(d, alo[mt], bhi + h * 2);
                    }
            }
        }
        __syncthreads();
    }

    const int g = lane >> 2, tig = lane & 3;
#pragma unroll
    for (int mt = 0; mt < 2; ++mt) {
#pragma unroll
        for (int nt = 0; nt < 8; ++nt) {
            const int col = nTile + wn * 64 + nt * 8 + tig * 2;
            const int r0 = mTile + wm * 32 + mt * 16 + g;
            const int r1 = r0 + 8;
            float* d = acc[mt][nt];
            if (mode == 0) {
                float2 bv = *(const float2*)(bias + col);
                *(float2*)(C + (size_t)r0 * DIM + col) =
                    make_float2(d[0] + bv.x, d[1] + bv.y);
                *(float2*)(C + (size_t)r1 * DIM + col) =
                    make_float2(d[2] + bv.x, d[3] + bv.y);
            } else if (mode == 1) {
                float2 bv = *(const float2*)(bias + col);
                float2 i0 = *(const float2*)(auxIn + (size_t)r0 * DIM + col);
                float2 i1 = *(const float2*)(auxIn + (size_t)r1 * DIM + col);
                float g0 = 1.f / (1.f + __expf(-(d[0] + bv.x)));
                float g1 = 1.f / (1.f + __expf(-(d[1] + bv.y)));
                float g2 = 1.f / (1.f + __expf(-(d[2] + bv.x)));
                float g3 = 1.f / (1.f + __expf(-(d[3] + bv.y)));
                *(float2*)(C + (size_t)r0 * DIM + col) = make_float2(g0, g1);
                *(float2*)(C + (size_t)r1 * DIM + col) = make_float2(g2, g3);
                *(float2*)(auxOut + (size_t)r0 * DIM + col) =
                    make_float2((1.f - g0) * i0.x, (1.f - g1) * i0.y);
                *(float2*)(auxOut + (size_t)r1 * DIM + col) =
                    make_float2((1.f - g2) * i1.x, (1.f - g3) * i1.y);
            } else {
                *(float2*)(C + (size_t)r0 * DIM + col) = make_float2(d[0], d[1]);
                *(float2*)(C + (size_t)r1 * DIM + col) = make_float2(d[2], d[3]);
            }
        }
    }
}

// ================= persistent state recurrence (v8: 2 barriers/step) =================
// state_t = tanh( y_{t-1} @ A^T + P_t ),  y_t = gate_{t+1} (*) state_t  (producer-folded)
// 128 co-resident CTAs, 8 output columns each, A slice in SMEM.
// v8 vs v5: EVERY warp polls the 128 flags itself (no poll barrier, poll+stage
// overlap across warps), and only two __syncthreads per step (post-stage, post-red).
// The finisher's red[] reads are protected by the NEXT step's post-stage barrier.
// Flag publish semantics identical to v5: stcg y/state, per-thread threadfence,
// __syncwarp, lane-0 volatile flag store.
#define REC_SMEM ((REC_COLS * DIM + BATCH * DIM + 8 * 16) * 4)

__global__ __launch_bounds__(256, 1)
void recurrence_kernel(const float* __restrict__ gate, const float* __restrict__ P,
                       const float* __restrict__ Amat, float* __restrict__ state)
{
    extern __shared__ float sh[];
    float* Asub = sh;                        // [REC_COLS][DIM]
    float* xs   = sh + REC_COLS * DIM;       // [BATCH][DIM]  (y_{t-1})
    float* red  = xs + BATCH * DIM;          // [8 warps][16]

    const int tid = threadIdx.x;
    const int warp = tid >> 5, lane = tid & 31;
    const int col0 = blockIdx.x * REC_COLS;
    const int cg = warp & 1;      // column group (4 cols)
    const int ks = warp >> 1;     // k slice (256 floats)

    for (int i = tid; i < REC_COLS * DIM / 4; i += 256) {
        int c = i >> 8, k4 = i & 255;
        ((float4*)(Asub + c * DIM))[k4] =
            ((const float4*)(Amat + (size_t)(col0 + c) * DIM))[k4];
    }

    const int f_cg = tid >> 4, f_bb = (tid >> 2) & 3, f_c = tid & 3;
    const int f_col = col0 + f_cg * 4 + f_c;

    int pbb[4], pk4[4];
#pragma unroll
    for (int j = 0; j < 4; ++j) {
        int idx = tid + j * 256;
        pbb[j] = idx >> 8;
        pk4[j] = idx & 255;
    }

    __syncthreads();

    for (int t = 0; t < SEQ; ++t) {
        // ---- finisher prefetch (warp 0; independent of y availability) ----
        float pval = 0.f, gval = 0.f;
        if (tid < 32) {
            pval = P[((size_t)f_bb * SEQ + t) * DIM + f_col];
            if (t + 1 < SEQ)
                gval = gate[((size_t)f_bb * SEQ + (t + 1)) * DIM + f_col];
        }

        // ---- per-warp poll: all CTAs published y_{t-1} (no barrier after) ----
        if (t > 0) {
            unsigned tgt = (unsigned)t;
            bool ok;
            do {
                bool good = true;
#pragma unroll
                for (int j = 0; j < 4; ++j) {
                    unsigned f = *(volatile const unsigned*)
                        &g_flags[(lane + 32 * j) * FLAG_STRIDE];
                    good = good && (f >= tgt);
                }
                ok = __all_sync(0xffffffffu, good);
            } while (!ok);
        }

        // ---- stage y_{t-1} into SMEM (own slice; poll already passed) ----
        if (t == 0) {
#pragma unroll
            for (int j = 0; j < 4; ++j)
                ((float4*)(xs + pbb[j] * DIM))[pk4[j]] = make_float4(0.f, 0.f, 0.f, 0.f);
        } else {
#pragma unroll
            for (int j = 0; j < 4; ++j) {
                float4 y4 = __ldcg(&((const float4*)(g_y + ((size_t)pbb[j] * SEQ + t - 1) * DIM))[pk4[j]]);
                ((float4*)(xs + pbb[j] * DIM))[pk4[j]] = y4;
            }
        }
        __syncthreads();                         // bar_A: xs ready (and red(t-1) free)

        // ---- partial dots: 4 batches x 4 cols over 256-float k slice ----
        float acc[4][4];
#pragma unroll
        for (int bb = 0; bb < 4; ++bb)
#pragma unroll
            for (int c = 0; c < 4; ++c) acc[bb][c] = 0.f;

#pragma unroll
        for (int i = 0; i < 2; ++i) {
            int k4 = ks * 64 + i * 32 + lane;
            float4 x4[4];
#pragma unroll
            for (int bb = 0; bb < 4; ++bb)
                x4[bb] = ((const float4*)(xs + bb * DIM))[k4];
#pragma unroll
            for (int c = 0; c < 4; ++c) {
                float4 a4 = ((const float4*)(Asub + (cg * 4 + c) * DIM))[k4];
#pragma unroll
                for (int bb = 0; bb < 4; ++bb) {
                    acc[bb][c] += x4[bb].x * a4.x + x4[bb].y * a4.y +
                                  x4[bb].z * a4.z + x4[bb].w * a4.w;
                }
            }
        }
#pragma unroll
        for (int bb = 0; bb < 4; ++bb)
#pragma unroll
            for (int c = 0; c < 4; ++c) {
                float v = acc[bb][c];
#pragma unroll
                for (int off = 16; off; off >>= 1)
                    v += __shfl_xor_sync(0xffffffffu, v, off);
                if (lane == 0) red[warp * 16 + bb * 4 + c] = v;
            }
        __syncthreads();                         // bar_B: red ready

        // ---- finisher (warp 0): sum, tanh, publish, fence, flag ----
        if (tid < 32) {
            float s = 0.f;
#pragma unroll
            for (int k = 0; k < 4; ++k)
                s += red[(k * 2 + f_cg) * 16 + f_bb * 4 + f_c];
            float sv = tanhf(s + pval);
            size_t idx = ((size_t)f_bb * SEQ + t) * DIM + f_col;
            __stcg(&state[idx], sv);
            if (t + 1 < SEQ)
                __stcg(&g_y[idx], sv * gval);
            __threadfence();
            __syncwarp();
            if (tid == 0)
                *(volatile unsigned*)&g_flags[blockIdx.x * FLAG_STRIDE] = (unsigned)(t + 1);
        }
        // no trailing barrier: next-iter bar_A gates red/xs reuse.
    }
}

__global__ void reset_flags()
{
    int i = threadIdx.x;
    if (i < REC_CTAS * FLAG_STRIDE) g_flags[i] = 0u;
}

// ================= launch =================
extern "C" void kernel_launch(void* const* d_in, const int* in_sizes, int n_in,
                              void* d_out, int out_size)
{
    const float* q     = (const float*)d_in[0];
    const float* k     = (const float*)d_in[1];
    const float* v     = (const float*)d_in[2];
    const float* Wi    = (const float*)d_in[3];
    const float* bi    = (const float*)d_in[4];
    const float* Wg    = (const float*)d_in[5];
    const float* bg    = (const float*)d_in[6];
    const float* A     = (const float*)d_in[7];
    const float* Bm    = (const float*)d_in[8];
    const float* Wo    = (const float*)d_in[9];
    const float* bo    = (const float*)d_in[10];
    const float* decay = (const float*)d_in[11];

    float *ret, *inp, *gate, *u, *p, *state;
    cudaGetSymbolAddress((void**)&ret,   g_ret);
    cudaGetSymbolAddress((void**)&inp,   g_inp);
    cudaGetSymbolAddress((void**)&gate,  g_gate);
    cudaGetSymbolAddress((void**)&u,     g_u);
    cudaGetSymbolAddress((void**)&p,     g_p);
    cudaGetSymbolAddress((void**)&state, g_state);

    cudaFuncSetAttribute(recurrence_kernel,
                         cudaFuncAttributeMaxDynamicSharedMemorySize, REC_SMEM);
    cudaFuncSetAttribute(mma_gemm,
                         cudaFuncAttributeMaxDynamicSharedMemorySize, GM_SMEM);

    dim3 sg(DIM / 256, NCHUNK, BATCH);
    scan_pass1<<<sg, 256>>>(k, v, decay);
    scan_pass2<<<dim3(DIM / 256, BATCH), 256>>>(decay);
    scan_pass3<<<sg, 256>>>(q, k, v, decay);

    dim3 gg(DIM / 128, MROWS / 128);   // (8, 64)
    // inp = ret @ Wi^T + bi
    mma_gemm<<<gg, 256, GM_SMEM>>>(ret, Wi, nullptr, nullptr, bi, inp,
                                   nullptr, nullptr, 0, 0);
    // gate = sigmoid(inp @ Wg^T + bg); u = (1-gate) * inp
    mma_gemm<<<gg, 256, GM_SMEM>>>(inp, Wg, nullptr, nullptr, bg, gate,
                                   inp, u, 1, 0);
    // p = u @ A^T + inp @ Bm^T   (fused dual accumulation)
    mma_gemm<<<gg, 256, GM_SMEM>>>(u, A, inp, Bm, nullptr, p,
                                   nullptr, nullptr, 3, 1);

    reset_flags<<<1, 1024>>>();
    recurrence_kernel<<<REC_CTAS, 256, REC_SMEM>>>(gate, p, A, state);

    // out = state @ Wo^T + bo
    mma_gemm<<<gg, 256, GM_SMEM>>>(state, Wo, nullptr, nullptr, bo, (float*)d_out,
                                   nullptr, nullptr, 0, 0);
}

// round 12
// speedup vs baseline: 1.6763x; 1.6763x over previous
#include <cuda_runtime.h>
#include <cuda_bf16.h>
#include <math.h>
#include <stdint.h>

#define BATCH 4
#define SEQ   2048
#define DIM   1024
#define NCHUNK 16
#define CHUNK  128          // SEQ / NCHUNK
#define MROWS  (BATCH * SEQ)   // 8192

// ---------------- scratch (static device globals; no allocation) ----------------
__device__ float g_ret  [(size_t)MROWS * DIM];
__device__ float g_inp  [(size_t)MROWS * DIM];
__device__ float g_gate [(size_t)MROWS * DIM];
__device__ float g_u    [(size_t)MROWS * DIM];
__device__ float g_p    [(size_t)MROWS * DIM];
__device__ float g_state[(size_t)MROWS * DIM];
__device__ float g_y    [(size_t)MROWS * DIM];   // y_t = gate_{t+1} * state_t

// pre-converted bf16 weight splits: slots 0=Wi 1=Wg 2=A 3=Bm 4=Wo
__device__ __nv_bfloat16 g_whi[5][(size_t)DIM * DIM];
__device__ __nv_bfloat16 g_wlo[5][(size_t)DIM * DIM];

#define REC_CTAS 128
#define REC_COLS 8
#define FLAG_STRIDE 8
__device__ unsigned int g_flags[REC_CTAS * FLAG_STRIDE];

__device__ float g_E   [BATCH * NCHUNK * DIM];
__device__ float g_cin [BATCH * NCHUNK * DIM];

// ---------------- helpers ----------------
__device__ __forceinline__ uint32_t smem_u32(const void* p) {
    uint32_t a;
    asm("{ .reg .u64 t; cvta.to.shared.u64 t, %1; cvt.u32.u64 %0, t; }"
        : "=r"(a) : "l"(p));
    return a;
}
__device__ __forceinline__ void ldm4(uint32_t* r, uint32_t addr) {
    asm volatile("ldmatrix.sync.aligned.m8n8.x4.shared.b16 {%0,%1,%2,%3}, [%4];"
                 : "=r"(r[0]), "=r"(r[1]), "=r"(r[2]), "=r"(r[3]) : "r"(addr));
}
__device__ __forceinline__ void mma16816(float* d, const uint32_t* a, const uint32_t* b) {
    asm volatile("mma.sync.aligned.m16n8k16.row.col.f32.bf16.bf16.f32 "
                 "{%0,%1,%2,%3}, {%4,%5,%6,%7}, {%8,%9}, {%0,%1,%2,%3};"
                 : "+f"(d[0]), "+f"(d[1]), "+f"(d[2]), "+f"(d[3])
                 : "r"(a[0]), "r"(a[1]), "r"(a[2]), "r"(a[3]),
                   "r"(b[0]), "r"(b[1]));
}

// ---------------- weight pre-conversion (bit-identical to in-GEMM split) ----------------
__global__ void cvt_w(const float* __restrict__ W, __nv_bfloat16* __restrict__ hi,
                      __nv_bfloat16* __restrict__ lo)
{
    int i = blockIdx.x * 256 + threadIdx.x;          // float4 index, 262144 total
    float4 v = ((const float4*)W)[i];
    uint32_t u0 = __float_as_uint(v.x), u1 = __float_as_uint(v.y);
    uint32_t u2 = __float_as_uint(v.z), u3 = __float_as_uint(v.w);
    uint2 h, l;
    h.x = (u0 >> 16) | (u1 & 0xFFFF0000u);
    h.y = (u2 >> 16) | (u3 & 0xFFFF0000u);
    float l0 = v.x - __uint_as_float(u0 & 0xFFFF0000u);
    float l1 = v.y - __uint_as_float(u1 & 0xFFFF0000u);
    float l2 = v.z - __uint_as_float(u2 & 0xFFFF0000u);
    float l3 = v.w - __uint_as_float(u3 & 0xFFFF0000u);
    asm("cvt.rn.satfinite.bf16x2.f32 %0, %1, %2;" : "=r"(l.x) : "f"(l1), "f"(l0));
    asm("cvt.rn.satfinite.bf16x2.f32 %0, %1, %2;" : "=r"(l.y) : "f"(l3), "f"(l2));
    ((uint2*)hi)[i] = h;
    ((uint2*)lo)[i] = l;
}

// ---------------- retention scan ----------------
__global__ void scan_pass1(const float* __restrict__ K, const float* __restrict__ V,
                           const float* __restrict__ decay)
{
    int d = blockIdx.x * 256 + threadIdx.x;
    int c = blockIdx.y;
    int b = blockIdx.z;
    float dec = decay[d >> 6];
    size_t base = ((size_t)b * SEQ + (size_t)c * CHUNK) * DIM + d;
    const float* kp = K + base;
    const float* vp = V + base;
    float r = 0.f;
#pragma unroll 8
    for (int i = 0; i < CHUNK; ++i)
        r = dec * r + kp[(size_t)i * DIM] * vp[(size_t)i * DIM];
    g_E[((size_t)b * NCHUNK + c) * DIM + d] = r;
}

__global__ void scan_pass2(const float* __restrict__ decay)
{
    int d = blockIdx.x * 256 + threadIdx.x;
    int b = blockIdx.y;
    float dec = decay[d >> 6];
    float decC = 1.f;
#pragma unroll
    for (int i = 0; i < CHUNK; ++i) decC *= dec;
    float carry = 0.f;
#pragma unroll
    for (int c = 0; c < NCHUNK; ++c) {
        size_t idx = ((size_t)b * NCHUNK + c) * DIM + d;
        g_cin[idx] = carry;
        carry = carry * decC + g_E[idx];
    }
}

__global__ void scan_pass3(const float* __restrict__ Q, const float* __restrict__ K,
                           const float* __restrict__ V, const float* __restrict__ decay)
{
    int d = blockIdx.x * 256 + threadIdx.x;
    int c = blockIdx.y;
    int b = blockIdx.z;
    float dec = decay[d >> 6];
    size_t base = ((size_t)b * SEQ + (size_t)c * CHUNK) * DIM + d;
    const float* qp = Q + base;
    const float* kp = K + base;
    const float* vp = V + base;
    float* rp = g_ret + base;
    float r = g_cin[((size_t)b * NCHUNK + c) * DIM + d];
#pragma unroll 8
    for (int i = 0; i < CHUNK; ++i) {
        r = dec * r + kp[(size_t)i * DIM] * vp[(size_t)i * DIM];
        rp[(size_t)i * DIM] = qp[(size_t)i * DIM] * r;
    }
}

// ================= pipelined mma.sync split-bf16 GEMM =================
// C[m,n] = sum_k X[m,k] * W[n,k]  (+ optional second pair accumulated)
// D = Xhi*Whi + Xhi*Wlo + Xlo*Whi, fp32 register accumulators.
// X split computed in-kernel; W side uses PRE-CONVERTED bf16 hi/lo tensors
// (direct LDG.128, no cvt). Tile 128x128/CTA, BK=32, 8 warps (4m x 2n),
// double-buffered dynamic SMEM, 1 barrier per chunk.
#define GM_LDS    40                        // padded row elements: 80B stride
#define GM_TILE_B (128 * GM_LDS * 2)        // 10240 B per (tile,part)
#define GM_BUF_B  (4 * GM_TILE_B)           // Ahi|Alo|Bhi|Blo = 40960 B
#define GM_SMEM   (2 * GM_BUF_B)            // 81920 B

__device__ __forceinline__ void ld_cvt(uint32_t* r, const float* __restrict__ src,
                                       int rowBase, int kBase, int tid)
{
    const int row = tid >> 1;
    const int cb  = (tid & 1) * 16;
    const float4* sp = (const float4*)(src + (size_t)(rowBase + row) * DIM + kBase + cb);
#pragma unroll
    for (int j = 0; j < 4; ++j) {
        float4 v = sp[j];
        uint32_t u0 = __float_as_uint(v.x), u1 = __float_as_uint(v.y);
        uint32_t u2 = __float_as_uint(v.z), u3 = __float_as_uint(v.w);
        r[j*4+0] = (u0 >> 16) | (u1 & 0xFFFF0000u);
        r[j*4+1] = (u2 >> 16) | (u3 & 0xFFFF0000u);
        float l0 = v.x - __uint_as_float(u0 & 0xFFFF0000u);
        float l1 = v.y - __uint_as_float(u1 & 0xFFFF0000u);
        float l2 = v.z - __uint_as_float(u2 & 0xFFFF0000u);
        float l3 = v.w - __uint_as_float(u3 & 0xFFFF0000u);
        asm("cvt.rn.satfinite.bf16x2.f32 %0, %1, %2;" : "=r"(r[j*4+2]) : "f"(l1), "f"(l0));
        asm("cvt.rn.satfinite.bf16x2.f32 %0, %1, %2;" : "=r"(r[j*4+3]) : "f"(l3), "f"(l2));
    }
}

__device__ __forceinline__ void sts_tile(char* hiT, char* loT, const uint32_t* r, int tid)
{
    const int row = tid >> 1;
    const int cb  = (tid & 1) * 16;
#pragma unroll
    for (int j = 0; j < 4; ++j) {
        int bo = 2 * (row * GM_LDS + cb + j * 4);
        *(uint32_t*)(hiT + bo)     = r[j*4+0];
        *(uint32_t*)(hiT + bo + 4) = r[j*4+1];
        *(uint32_t*)(loT + bo)     = r[j*4+2];
        *(uint32_t*)(loT + bo + 4) = r[j*4+3];
    }
}

// B side: direct bf16 hi/lo loads (no conversion), 16B-aligned vector ops.
__device__ __forceinline__ void ld_b(uint4* r, const __nv_bfloat16* __restrict__ Whi,
                                     const __nv_bfloat16* __restrict__ Wlo,
                                     int rowBase, int kBase, int tid)
{
    const int row = tid >> 1;
    const int cb  = (tid & 1) * 16;
    const uint4* hp = (const uint4*)(Whi + (size_t)(rowBase + row) * DIM + kBase + cb);
    const uint4* lp = (const uint4*)(Wlo + (size_t)(rowBase + row) * DIM + kBase + cb);
    r[0] = hp[0]; r[1] = hp[1];
    r[2] = lp[0]; r[3] = lp[1];
}
__device__ __forceinline__ void sts_b(char* hiT, char* loT, const uint4* r, int tid)
{
    const int row = tid >> 1;
    const int cb  = (tid & 1) * 16;
    const int bo  = 2 * (row * GM_LDS + cb);    // 80B row stride: 16B-aligned
    *(uint4*)(hiT + bo)      = r[0];
    *(uint4*)(hiT + bo + 16) = r[1];
    *(uint4*)(loT + bo)      = r[2];
    *(uint4*)(loT + bo + 16) = r[3];
}

__global__ __launch_bounds__(256)
void mma_gemm(const float* __restrict__ X1,
              const __nv_bfloat16* __restrict__ W1hi, const __nv_bfloat16* __restrict__ W1lo,
              const float* __restrict__ X2,
              const __nv_bfloat16* __restrict__ W2hi, const __nv_bfloat16* __restrict__ W2lo,
              const float* __restrict__ bias, float* __restrict__ C,
              const float* __restrict__ auxIn, float* __restrict__ auxOut,
              int mode, int dual)
{
    extern __shared__ char dyn[];
    const uint32_t sb = smem_u32(dyn);
    const int tid = threadIdx.x;
    const int wid = tid >> 5, lane = tid & 31;
    const int wm = wid >> 1;
    const int wn = wid & 1;
    const int nTile = blockIdx.x * 128;
    const int mTile = blockIdx.y * 128;

    float acc[2][8][4];
#pragma unroll
    for (int mt = 0; mt < 2; ++mt)
#pragma unroll
        for (int nt = 0; nt < 8; ++nt)
#pragma unroll
            for (int r = 0; r < 4; ++r) acc[mt][nt][r] = 0.f;

    const uint32_t aRow  = wm * 32 + (lane & 15);
    const uint32_t aKoff = (lane >> 4) * 8;
    const uint32_t bRow  = wn * 64 + (lane & 7) + ((lane >> 4) << 3);
    const uint32_t bKoff = ((lane >> 3) & 1) * 8;

    uint32_t rA[16];
    uint4 rB[4];

    // prologue: chunk 0 -> buf0
    ld_cvt(rA, X1, mTile, 0, tid);
    ld_b(rB, W1hi, W1lo, nTile, 0, tid);
    sts_tile(dyn, dyn + GM_TILE_B, rA, tid);
    sts_b(dyn + 2 * GM_TILE_B, dyn + 3 * GM_TILE_B, rB, tid);
    __syncthreads();

    const int nCh = dual ? 64 : 32;
    for (int c = 0; c < nCh; ++c) {
        const int buf = c & 1;

        if (c + 1 < nCh) {
            const int c1 = c + 1;
            const float* X = (c1 >= 32) ? X2 : X1;
            const __nv_bfloat16* Whi = (c1 >= 32) ? W2hi : W1hi;
            const __nv_bfloat16* Wlo = (c1 >= 32) ? W2lo : W1lo;
            const int kB = (c1 & 31) * 32;
            ld_cvt(rA, X, mTile, kB, tid);
            ld_b(rB, Whi, Wlo, nTile, kB, tid);
            char* nb = dyn + (buf ^ 1) * GM_BUF_B;
            sts_tile(nb, nb + GM_TILE_B, rA, tid);
            sts_b(nb + 2 * GM_TILE_B, nb + 3 * GM_TILE_B, rB, tid);
        }

        const uint32_t base = sb + buf * GM_BUF_B;
#pragma unroll
        for (int kk = 0; kk < 2; ++kk) {
            uint32_t ahi[2][4], alo[2][4];
#pragma unroll
            for (int mt = 0; mt < 2; ++mt) {
                uint32_t off = 2u * ((aRow + mt * 16) * GM_LDS + kk * 16 + aKoff);
                ldm4(ahi[mt], base + off);
                ldm4(alo[mt], base + GM_TILE_B + off);
            }
#pragma unroll
            for (int ng = 0; ng < 4; ++ng) {
                uint32_t bhi[4], blo[4];
                uint32_t off = 2u * ((bRow + ng * 16) * GM_LDS + kk * 16 + bKoff);
                ldm4(bhi, base + 2 * GM_TILE_B + off);
                ldm4(blo, base + 3 * GM_TILE_B + off);
#pragma unroll
                for (int mt = 0; mt < 2; ++mt)
#pragma unroll
                    for (int h = 0; h < 2; ++h) {
                        float* d = acc[mt][ng * 2 + h];
                        mma16816(d, ahi[mt], bhi + h * 2);
                        mma16816(d, ahi[mt], blo + h * 2);
                        mma16816(d, alo[mt], bhi + h * 2);
                    }
            }
        }
        __syncthreads();
    }

    const int g = lane >> 2, tig = lane & 3;
#pragma unroll
    for (int mt = 0; mt < 2; ++mt) {
#pragma unroll
        for (int nt = 0; nt < 8; ++nt) {
            const int col = nTile + wn * 64 + nt * 8 + tig * 2;
            const int r0 = mTile + wm * 32 + mt * 16 + g;
            const int r1 = r0 + 8;
            float* d = acc[mt][nt];
            if (mode == 0) {
                float2 bv = *(const float2*)(bias + col);
                *(float2*)(C + (size_t)r0 * DIM + col) =
                    make_float2(d[0] + bv.x, d[1] + bv.y);
                *(float2*)(C + (size_t)r1 * DIM + col) =
                    make_float2(d[2] + bv.x, d[3] + bv.y);
            } else if (mode == 1) {
                float2 bv = *(const float2*)(bias + col);
                float2 i0 = *(const float2*)(auxIn + (size_t)r0 * DIM + col);
                float2 i1 = *(const float2*)(auxIn + (size_t)r1 * DIM + col);
                float g0 = 1.f / (1.f + __expf(-(d[0] + bv.x)));
                float g1 = 1.f / (1.f + __expf(-(d[1] + bv.y)));
                float g2 = 1.f / (1.f + __expf(-(d[2] + bv.x)));
                float g3 = 1.f / (1.f + __expf(-(d[3] + bv.y)));
                *(float2*)(C + (size_t)r0 * DIM + col) = make_float2(g0, g1);
                *(float2*)(C + (size_t)r1 * DIM + col) = make_float2(g2, g3);
                *(float2*)(auxOut + (size_t)r0 * DIM + col) =
                    make_float2((1.f - g0) * i0.x, (1.f - g1) * i0.y);
                *(float2*)(auxOut + (size_t)r1 * DIM + col) =
                    make_float2((1.f - g2) * i1.x, (1.f - g3) * i1.y);
            } else {
                *(float2*)(C + (size_t)r0 * DIM + col) = make_float2(d[0], d[1]);
                *(float2*)(C + (size_t)r1 * DIM + col) = make_float2(d[2], d[3]);
            }
        }
    }
}

// ================= persistent state recurrence (v5 — FROZEN, proven @6632) =================
#define REC_SMEM ((REC_COLS * DIM + BATCH * DIM + 8 * 16) * 4)

__global__ __launch_bounds__(256, 1)
void recurrence_kernel(const float* __restrict__ gate, const float* __restrict__ P,
                       const float* __restrict__ Amat, float* __restrict__ state)
{
    extern __shared__ float sh[];
    float* Asub = sh;
    float* xs   = sh + REC_COLS * DIM;
    float* red  = xs + BATCH * DIM;

    const int tid = threadIdx.x;
    const int warp = tid >> 5, lane = tid & 31;
    const int col0 = blockIdx.x * REC_COLS;
    const int cg = warp & 1;
    const int ks = warp >> 1;

    for (int i = tid; i < REC_COLS * DIM / 4; i += 256) {
        int c = i >> 8, k4 = i & 255;
        ((float4*)(Asub + c * DIM))[k4] =
            ((const float4*)(Amat + (size_t)(col0 + c) * DIM))[k4];
    }

    const int f_cg = tid >> 4, f_bb = (tid >> 2) & 3, f_c = tid & 3;
    const int f_col = col0 + f_cg * 4 + f_c;

    int pbb[4], pk4[4];
#pragma unroll
    for (int j = 0; j < 4; ++j) {
        int idx = tid + j * 256;
        pbb[j] = idx >> 8;
        pk4[j] = idx & 255;
    }

    __syncthreads();

    for (int t = 0; t < SEQ; ++t) {
        float pval = 0.f, gval = 0.f;
        if (tid < 32) {
            pval = P[((size_t)f_bb * SEQ + t) * DIM + f_col];
            if (t + 1 < SEQ)
                gval = gate[((size_t)f_bb * SEQ + (t + 1)) * DIM + f_col];
        }

        if (t > 0 && warp == 0) {
            unsigned tgt = (unsigned)t;
            bool ok;
            do {
                bool good = true;
#pragma unroll
                for (int j = 0; j < 4; ++j) {
                    unsigned f = *(volatile const unsigned*)
                        &g_flags[(lane + 32 * j) * FLAG_STRIDE];
                    good = good && (f >= tgt);
                }
                ok = __all_sync(0xffffffffu, good);
            } while (!ok);
        }
        __syncthreads();

        if (t == 0) {
#pragma unroll
            for (int j = 0; j < 4; ++j)
                ((float4*)(xs + pbb[j] * DIM))[pk4[j]] = make_float4(0.f, 0.f, 0.f, 0.f);
        } else {
#pragma unroll
            for (int j = 0; j < 4; ++j) {
                float4 y4 = __ldcg(&((const float4*)(g_y + ((size_t)pbb[j] * SEQ + t - 1) * DIM))[pk4[j]]);
                ((float4*)(xs + pbb[j] * DIM))[pk4[j]] = y4;
            }
        }
        __syncthreads();

        float acc[4][4];
#pragma unroll
        for (int bb = 0; bb < 4; ++bb)
#pragma unroll
            for (int c = 0; c < 4; ++c) acc[bb][c] = 0.f;

#pragma unroll
        for (int i = 0; i < 2; ++i) {
            int k4 = ks * 64 + i * 32 + lane;
            float4 x4[4];
#pragma unroll
            for (int bb = 0; bb < 4; ++bb)
                x4[bb] = ((const float4*)(xs + bb * DIM))[k4];
#pragma unroll
            for (int c = 0; c < 4; ++c) {
                float4 a4 = ((const float4*)(Asub + (cg * 4 + c) * DIM))[k4];
#pragma unroll
                for (int bb = 0; bb < 4; ++bb) {
                    acc[bb][c] += x4[bb].x * a4.x + x4[bb].y * a4.y +
                                  x4[bb].z * a4.z + x4[bb].w * a4.w;
                }
            }
        }
#pragma unroll
        for (int bb = 0; bb < 4; ++bb)
#pragma unroll
            for (int c = 0; c < 4; ++c) {
                float v = acc[bb][c];
#pragma unroll
                for (int off = 16; off; off >>= 1)
                    v += __shfl_xor_sync(0xffffffffu, v, off);
                acc[bb][c] = v;
            }
        if (lane == 0) {
#pragma unroll
            for (int bb = 0; bb < 4; ++bb)
#pragma unroll
                for (int c = 0; c < 4; ++c)
                    red[warp * 16 + bb * 4 + c] = acc[bb][c];
        }
        __syncthreads();

        if (tid < 32) {
            float s = 0.f;
#pragma unroll
            for (int k = 0; k < 4; ++k)
                s += red[(k * 2 + f_cg) * 16 + f_bb * 4 + f_c];
            float sv = tanhf(s + pval);
            size_t idx = ((size_t)f_bb * SEQ + t) * DIM + f_col;
            __stcg(&state[idx], sv);
            if (t + 1 < SEQ)
                __stcg(&g_y[idx], sv * gval);
            __threadfence();
        }
        __syncthreads();

        if (tid == 0)
            *(volatile unsigned*)&g_flags[blockIdx.x * FLAG_STRIDE] = (unsigned)(t + 1);
        __syncthreads();
    }
}

__global__ void reset_flags()
{
    int i = threadIdx.x;
    if (i < REC_CTAS * FLAG_STRIDE) g_flags[i] = 0u;
}

// ================= launch =================
extern "C" void kernel_launch(void* const* d_in, const int* in_sizes, int n_in,
                              void* d_out, int out_size)
{
    const float* q     = (const float*)d_in[0];
    const float* k     = (const float*)d_in[1];
    const float* v     = (const float*)d_in[2];
    const float* Wi    = (const float*)d_in[3];
    const float* bi    = (const float*)d_in[4];
    const float* Wg    = (const float*)d_in[5];
    const float* bg    = (const float*)d_in[6];
    const float* A     = (const float*)d_in[7];
    const float* Bm    = (const float*)d_in[8];
    const float* Wo    = (const float*)d_in[9];
    const float* bo    = (const float*)d_in[10];
    const float* decay = (const float*)d_in[11];

    float *ret, *inp, *gate, *u, *p, *state;
    cudaGetSymbolAddress((void**)&ret,   g_ret);
    cudaGetSymbolAddress((void**)&inp,   g_inp);
    cudaGetSymbolAddress((void**)&gate,  g_gate);
    cudaGetSymbolAddress((void**)&u,     g_u);
    cudaGetSymbolAddress((void**)&p,     g_p);
    cudaGetSymbolAddress((void**)&state, g_state);

    __nv_bfloat16 *whi, *wlo;
    cudaGetSymbolAddress((void**)&whi, g_whi);
    cudaGetSymbolAddress((void**)&wlo, g_wlo);
    const size_t WSZ = (size_t)DIM * DIM;

    cudaFuncSetAttribute(recurrence_kernel,
                         cudaFuncAttributeMaxDynamicSharedMemorySize, REC_SMEM);
    cudaFuncSetAttribute(mma_gemm,
                         cudaFuncAttributeMaxDynamicSharedMemorySize, GM_SMEM);

    // weight pre-conversion (bit-identical to in-kernel split)
    const int cg = (DIM * DIM / 4) / 256;   // 1024 blocks
    cvt_w<<<cg, 256>>>(Wi, whi + 0 * WSZ, wlo + 0 * WSZ);
    cvt_w<<<cg, 256>>>(Wg, whi + 1 * WSZ, wlo + 1 * WSZ);
    cvt_w<<<cg, 256>>>(A,  whi + 2 * WSZ, wlo + 2 * WSZ);
    cvt_w<<<cg, 256>>>(Bm, whi + 3 * WSZ, wlo + 3 * WSZ);
    cvt_w<<<cg, 256>>>(Wo, whi + 4 * WSZ, wlo + 4 * WSZ);

    dim3 sg(DIM / 256, NCHUNK, BATCH);
    scan_pass1<<<sg, 256>>>(k, v, decay);
    scan_pass2<<<dim3(DIM / 256, BATCH), 256>>>(decay);
    scan_pass3<<<sg, 256>>>(q, k, v, decay);

    dim3 gg(DIM / 128, MROWS / 128);   // (8, 64)
    // inp = ret @ Wi^T + bi
    mma_gemm<<<gg, 256, GM_SMEM>>>(ret, whi + 0 * WSZ, wlo + 0 * WSZ,
                                   nullptr, nullptr, nullptr,
                                   bi, inp, nullptr, nullptr, 0, 0);
    // gate = sigmoid(inp @ Wg^T + bg); u = (1-gate) * inp
    mma_gemm<<<gg, 256, GM_SMEM>>>(inp, whi + 1 * WSZ, wlo + 1 * WSZ,
                                   nullptr, nullptr, nullptr,
                                   bg, gate, inp, u, 1, 0);
    // p = u @ A^T + inp @ Bm^T   (fused dual accumulation)
    mma_gemm<<<gg, 256, GM_SMEM>>>(u, whi + 2 * WSZ, wlo + 2 * WSZ,
                                   inp, whi + 3 * WSZ, wlo + 3 * WSZ,
                                   nullptr, p, nullptr, nullptr, 3, 1);

    reset_flags<<<1, 1024>>>();
    recurrence_kernel<<<REC_CTAS, 256, REC_SMEM>>>(gate, p, A, state);

    // out = state @ Wo^T + bo
    mma_gemm<<<gg, 256, GM_SMEM>>>(state, whi + 4 * WSZ, wlo + 4 * WSZ,
                                   nullptr, nullptr, nullptr,
                                   bo, (float*)d_out, nullptr, nullptr, 0, 0);
}

// round 13
// speedup vs baseline: 1.7989x; 1.0731x over previous
#include <cuda_runtime.h>
#include <cuda_bf16.h>
#include <math.h>
#include <stdint.h>

#define BATCH 4
#define SEQ   2048
#define DIM   1024
#define NCHUNK 16
#define CHUNK  128          // SEQ / NCHUNK
#define MROWS  (BATCH * SEQ)   // 8192

// ---------------- scratch (static device globals; no allocation) ----------------
__device__ float g_inp  [(size_t)MROWS * DIM];
__device__ float g_gate [(size_t)MROWS * DIM];
__device__ float g_p    [(size_t)MROWS * DIM];
__device__ float g_y    [(size_t)MROWS * DIM];   // y_t = gate_{t+1} * state_t

// bf16 hi/lo operand chain (split is bit-identical to the old in-GEMM split)
__device__ __nv_bfloat16 g_rethi[(size_t)MROWS * DIM];
__device__ __nv_bfloat16 g_retlo[(size_t)MROWS * DIM];
__device__ __nv_bfloat16 g_inphi[(size_t)MROWS * DIM];
__device__ __nv_bfloat16 g_inplo[(size_t)MROWS * DIM];
__device__ __nv_bfloat16 g_uhi  [(size_t)MROWS * DIM];
__device__ __nv_bfloat16 g_ulo  [(size_t)MROWS * DIM];
__device__ __nv_bfloat16 g_sthi [(size_t)MROWS * DIM];
__device__ __nv_bfloat16 g_stlo [(size_t)MROWS * DIM];

// pre-converted bf16 weight splits: slots 0=Wi 1=Wg 2=A 3=Bm 4=Wo
__device__ __nv_bfloat16 g_whi[5][(size_t)DIM * DIM];
__device__ __nv_bfloat16 g_wlo[5][(size_t)DIM * DIM];

#define REC_CTAS 128
#define REC_COLS 8
#define FLAG_STRIDE 8
__device__ unsigned int g_flags[REC_CTAS * FLAG_STRIDE];

__device__ float g_E   [BATCH * NCHUNK * DIM];
__device__ float g_cin [BATCH * NCHUNK * DIM];

// ---------------- helpers ----------------
__device__ __forceinline__ uint32_t smem_u32(const void* p) {
    uint32_t a;
    asm("{ .reg .u64 t; cvta.to.shared.u64 t, %1; cvt.u32.u64 %0, t; }"
        : "=r"(a) : "l"(p));
    return a;
}
__device__ __forceinline__ void ldm4(uint32_t* r, uint32_t addr) {
    asm volatile("ldmatrix.sync.aligned.m8n8.x4.shared.b16 {%0,%1,%2,%3}, [%4];"
                 : "=r"(r[0]), "=r"(r[1]), "=r"(r[2]), "=r"(r[3]) : "r"(addr));
}
__device__ __forceinline__ void mma16816(float* d, const uint32_t* a, const uint32_t* b) {
    asm volatile("mma.sync.aligned.m16n8k16.row.col.f32.bf16.bf16.f32 "
                 "{%0,%1,%2,%3}, {%4,%5,%6,%7}, {%8,%9}, {%0,%1,%2,%3};"
                 : "+f"(d[0]), "+f"(d[1]), "+f"(d[2]), "+f"(d[3])
                 : "r"(a[0]), "r"(a[1]), "r"(a[2]), "r"(a[3]),
                   "r"(b[0]), "r"(b[1]));
}
#define CP16(dst, src) \
    asm volatile("cp.async.ca.shared.global [%0], [%1], 16;" \
                 :: "r"(dst), "l"(src) : "memory")
#define CP_COMMIT()   asm volatile("cp.async.commit_group;" ::: "memory")
#define CP_WAIT_ALL() asm volatile("cp.async.wait_group 0;" ::: "memory")

// split two fp32 into packed bf16x2 hi (truncate) and lo (rn residual) —
// bit-identical to the original in-GEMM ld_cvt split.
__device__ __forceinline__ void split2(float a, float b, uint32_t& hi, uint32_t& lo) {
    uint32_t ua = __float_as_uint(a), ub = __float_as_uint(b);
    hi = (ua >> 16) | (ub & 0xFFFF0000u);
    float ra = a - __uint_as_float(ua & 0xFFFF0000u);
    float rb = b - __uint_as_float(ub & 0xFFFF0000u);
    asm("cvt.rn.satfinite.bf16x2.f32 %0, %1, %2;" : "=r"(lo) : "f"(rb), "f"(ra));
}

// ---------------- weight pre-conversion ----------------
__global__ void cvt_w(const float* __restrict__ W, __nv_bfloat16* __restrict__ hi,
                      __nv_bfloat16* __restrict__ lo)
{
    int i = blockIdx.x * 256 + threadIdx.x;
    float4 v = ((const float4*)W)[i];
    uint2 h, l;
    split2(v.x, v.y, h.x, l.x);
    split2(v.z, v.w, h.y, l.y);
    ((uint2*)hi)[i] = h;
    ((uint2*)lo)[i] = l;
}

// ---------------- retention scan ----------------
__global__ void scan_pass1(const float* __restrict__ K, const float* __restrict__ V,
                           const float* __restrict__ decay)
{
    int d = blockIdx.x * 256 + threadIdx.x;
    int c = blockIdx.y;
    int b = blockIdx.z;
    float dec = decay[d >> 6];
    size_t base = ((size_t)b * SEQ + (size_t)c * CHUNK) * DIM + d;
    const float* kp = K + base;
    const float* vp = V + base;
    float r = 0.f;
#pragma unroll 8
    for (int i = 0; i < CHUNK; ++i)
        r = dec * r + kp[(size_t)i * DIM] * vp[(size_t)i * DIM];
    g_E[((size_t)b * NCHUNK + c) * DIM + d] = r;
}

__global__ void scan_pass2(const float* __restrict__ decay)
{
    int d = blockIdx.x * 256 + threadIdx.x;
    int b = blockIdx.y;
    float dec = decay[d >> 6];
    float decC = 1.f;
#pragma unroll
    for (int i = 0; i < CHUNK; ++i) decC *= dec;
    float carry = 0.f;
#pragma unroll
    for (int c = 0; c < NCHUNK; ++c) {
        size_t idx = ((size_t)b * NCHUNK + c) * DIM + d;
        g_cin[idx] = carry;
        carry = carry * decC + g_E[idx];
    }
}

__global__ void scan_pass3(const float* __restrict__ Q, const float* __restrict__ K,
                           const float* __restrict__ V, const float* __restrict__ decay)
{
    int d = blockIdx.x * 256 + threadIdx.x;
    int c = blockIdx.y;
    int b = blockIdx.z;
    float dec = decay[d >> 6];
    size_t base = ((size_t)b * SEQ + (size_t)c * CHUNK) * DIM + d;
    const float* qp = Q + base;
    const float* kp = K + base;
    const float* vp = V + base;
    float r = g_cin[((size_t)b * NCHUNK + c) * DIM + d];
#pragma unroll 8
    for (int i = 0; i < CHUNK; ++i) {
        r = dec * r + kp[(size_t)i * DIM] * vp[(size_t)i * DIM];
        float ret = qp[(size_t)i * DIM] * r;
        uint32_t u = __float_as_uint(ret);
        size_t idx = base + (size_t)i * DIM;
        *(uint16_t*)&g_rethi[idx] = (uint16_t)(u >> 16);
        float res = ret - __uint_as_float(u & 0xFFFF0000u);
        g_retlo[idx] = __float2bfloat16(res);
    }
}

// ================= cp.async pipelined bf16-native split GEMM =================
// C[m,n] = sum_k X[m,k]*W[n,k] (+ optional X2,W2 accumulated)
// D = Xhi*Whi + Xhi*Wlo + Xlo*Whi, fp32 register accumulators.
// ALL operands pre-split bf16 in gmem -> pure cp.async 16B copies, no cvt/STS.
// Tile 128x128/CTA, BK=32, 8 warps (4m x 2n), double-buffered, 1 barrier/chunk.
#define GM_LDS    40                        // padded row elements: 80B stride
#define GM_TILE_B (128 * GM_LDS * 2)        // 10240 B per (tile,part)
#define GM_BUF_B  (4 * GM_TILE_B)           // Ahi|Alo|Bhi|Blo = 40960 B
#define GM_SMEM   (2 * GM_BUF_B)            // 81920 B

__device__ __forceinline__ void cp_tile(uint32_t sHi, uint32_t sLo,
                                        const __nv_bfloat16* __restrict__ hi,
                                        const __nv_bfloat16* __restrict__ lo,
                                        int rowBase, int kBase, int tid)
{
    const int row = tid >> 1;
    const int cb  = (tid & 1) * 16;
    const __nv_bfloat16* gh = hi + (size_t)(rowBase + row) * DIM + kBase + cb;
    const __nv_bfloat16* gl = lo + (size_t)(rowBase + row) * DIM + kBase + cb;
    const uint32_t so = 2u * (row * GM_LDS + cb);
    CP16(sHi + so,      gh);
    CP16(sHi + so + 16, gh + 8);
    CP16(sLo + so,      gl);
    CP16(sLo + so + 16, gl + 8);
}

__global__ __launch_bounds__(256)
void mma_gemm(const __nv_bfloat16* __restrict__ X1hi, const __nv_bfloat16* __restrict__ X1lo,
              const __nv_bfloat16* __restrict__ W1hi, const __nv_bfloat16* __restrict__ W1lo,
              const __nv_bfloat16* __restrict__ X2hi, const __nv_bfloat16* __restrict__ X2lo,
              const __nv_bfloat16* __restrict__ W2hi, const __nv_bfloat16* __restrict__ W2lo,
              const float* __restrict__ bias, float* __restrict__ C,
              __nv_bfloat16* __restrict__ Chi, __nv_bfloat16* __restrict__ Clo,
              const float* __restrict__ auxIn,
              __nv_bfloat16* __restrict__ uHi, __nv_bfloat16* __restrict__ uLo,
              int mode, int dual)
{
    extern __shared__ char dyn[];
    const uint32_t sb = smem_u32(dyn);
    const int tid = threadIdx.x;
    const int wid = tid >> 5, lane = tid & 31;
    const int wm = wid >> 1;
    const int wn = wid & 1;
    const int nTile = blockIdx.x * 128;
    const int mTile = blockIdx.y * 128;

    float acc[2][8][4];
#pragma unroll
    for (int mt = 0; mt < 2; ++mt)
#pragma unroll
        for (int nt = 0; nt < 8; ++nt)
#pragma unroll
            for (int r = 0; r < 4; ++r) acc[mt][nt][r] = 0.f;

    const uint32_t aRow  = wm * 32 + (lane & 15);
    const uint32_t aKoff = (lane >> 4) * 8;
    const uint32_t bRow  = wn * 64 + (lane & 7) + ((lane >> 4) << 3);
    const uint32_t bKoff = ((lane >> 3) & 1) * 8;

    // prologue: chunk 0 -> buf0
    cp_tile(sb, sb + GM_TILE_B, X1hi, X1lo, mTile, 0, tid);
    cp_tile(sb + 2 * GM_TILE_B, sb + 3 * GM_TILE_B, W1hi, W1lo, nTile, 0, tid);
    CP_COMMIT();
    CP_WAIT_ALL();
    __syncthreads();

    const int nCh = dual ? 64 : 32;
    for (int c = 0; c < nCh; ++c) {
        const int buf = c & 1;

        // async prefetch of chunk c+1 into the other buffer
        if (c + 1 < nCh) {
            const int c1 = c + 1;
            const __nv_bfloat16* Xh = (c1 >= 32) ? X2hi : X1hi;
            const __nv_bfloat16* Xl = (c1 >= 32) ? X2lo : X1lo;
            const __nv_bfloat16* Wh = (c1 >= 32) ? W2hi : W1hi;
            const __nv_bfloat16* Wl = (c1 >= 32) ? W2lo : W1lo;
            const int kB = (c1 & 31) * 32;
            const uint32_t nb = sb + (buf ^ 1) * GM_BUF_B;
            cp_tile(nb, nb + GM_TILE_B, Xh, Xl, mTile, kB, tid);
            cp_tile(nb + 2 * GM_TILE_B, nb + 3 * GM_TILE_B, Wh, Wl, nTile, kB, tid);
            CP_COMMIT();
        }

        // MMA on current buffer
        const uint32_t base = sb + buf * GM_BUF_B;
#pragma unroll
        for (int kk = 0; kk < 2; ++kk) {
            uint32_t ahi[2][4], alo[2][4];
#pragma unroll
            for (int mt = 0; mt < 2; ++mt) {
                uint32_t off = 2u * ((aRow + mt * 16) * GM_LDS + kk * 16 + aKoff);
                ldm4(ahi[mt], base + off);
                ldm4(alo[mt], base + GM_TILE_B + off);
            }
#pragma unroll
            for (int ng = 0; ng < 4; ++ng) {
                uint32_t bhi[4], blo[4];
                uint32_t off = 2u * ((bRow + ng * 16) * GM_LDS + kk * 16 + bKoff);
                ldm4(bhi, base + 2 * GM_TILE_B + off);
                ldm4(blo, base + 3 * GM_TILE_B + off);
#pragma unroll
                for (int mt = 0; mt < 2; ++mt)
#pragma unroll
                    for (int h = 0; h < 2; ++h) {
                        float* d = acc[mt][ng * 2 + h];
                        mma16816(d, ahi[mt], bhi + h * 2);
                        mma16816(d, ahi[mt], blo + h * 2);
                        mma16816(d, alo[mt], bhi + h * 2);
                    }
            }
        }
        if (c + 1 < nCh) CP_WAIT_ALL();
        __syncthreads();
    }

    // ---- epilogue from register accumulators ----
    const int g = lane >> 2, tig = lane & 3;
#pragma unroll
    for (int mt = 0; mt < 2; ++mt) {
#pragma unroll
        for (int nt = 0; nt < 8; ++nt) {
            const int col = nTile + wn * 64 + nt * 8 + tig * 2;
            const int r0 = mTile + wm * 32 + mt * 16 + g;
            const int r1 = r0 + 8;
            float* d = acc[mt][nt];
            if (mode == 0) {
                float2 bv = *(const float2*)(bias + col);
                float2 o0 = make_float2(d[0] + bv.x, d[1] + bv.y);
                float2 o1 = make_float2(d[2] + bv.x, d[3] + bv.y);
                *(float2*)(C + (size_t)r0 * DIM + col) = o0;
                *(float2*)(C + (size_t)r1 * DIM + col) = o1;
                if (Chi) {
                    uint32_t h0, l0, h1, l1;
                    split2(o0.x, o0.y, h0, l0);
                    split2(o1.x, o1.y, h1, l1);
                    *(uint32_t*)(Chi + (size_t)r0 * DIM + col) = h0;
                    *(uint32_t*)(Clo + (size_t)r0 * DIM + col) = l0;
                    *(uint32_t*)(Chi + (size_t)r1 * DIM + col) = h1;
                    *(uint32_t*)(Clo + (size_t)r1 * DIM + col) = l1;
                }
            } else if (mode == 1) {
                float2 bv = *(const float2*)(bias + col);
                float2 i0 = *(const float2*)(auxIn + (size_t)r0 * DIM + col);
                float2 i1 = *(const float2*)(auxIn + (size_t)r1 * DIM + col);
                float g0 = 1.f / (1.f + __expf(-(d[0] + bv.x)));
                float g1 = 1.f / (1.f + __expf(-(d[1] + bv.y)));
                float g2 = 1.f / (1.f + __expf(-(d[2] + bv.x)));
                float g3 = 1.f / (1.f + __expf(-(d[3] + bv.y)));
                *(float2*)(C + (size_t)r0 * DIM + col) = make_float2(g0, g1);
                *(float2*)(C + (size_t)r1 * DIM + col) = make_float2(g2, g3);
                float u0 = (1.f - g0) * i0.x, u1 = (1.f - g1) * i0.y;
                float u2 = (1.f - g2) * i1.x, u3 = (1.f - g3) * i1.y;
                uint32_t h0, l0, h1, l1;
                split2(u0, u1, h0, l0);
                split2(u2, u3, h1, l1);
                *(uint32_t*)(uHi + (size_t)r0 * DIM + col) = h0;
                *(uint32_t*)(uLo + (size_t)r0 * DIM + col) = l0;
                *(uint32_t*)(uHi + (size_t)r1 * DIM + col) = h1;
                *(uint32_t*)(uLo + (size_t)r1 * DIM + col) = l1;
            } else {
                *(float2*)(C + (size_t)r0 * DIM + col) = make_float2(d[0], d[1]);
                *(float2*)(C + (size_t)r1 * DIM + col) = make_float2(d[2], d[3]);
            }
        }
    }
}

// ================= persistent state recurrence (v5 frozen; finisher emits bf16 split) =================
#define REC_SMEM ((REC_COLS * DIM + BATCH * DIM + 8 * 16) * 4)

__global__ __launch_bounds__(256, 1)
void recurrence_kernel(const float* __restrict__ gate, const float* __restrict__ P,
                       const float* __restrict__ Amat,
                       __nv_bfloat16* __restrict__ stHi, __nv_bfloat16* __restrict__ stLo)
{
    extern __shared__ float sh[];
    float* Asub = sh;
    float* xs   = sh + REC_COLS * DIM;
    float* red  = xs + BATCH * DIM;

    const int tid = threadIdx.x;
    const int warp = tid >> 5, lane = tid & 31;
    const int col0 = blockIdx.x * REC_COLS;
    const int cg = warp & 1;
    const int ks = warp >> 1;

    for (int i = tid; i < REC_COLS * DIM / 4; i += 256) {
        int c = i >> 8, k4 = i & 255;
        ((float4*)(Asub + c * DIM))[k4] =
            ((const float4*)(Amat + (size_t)(col0 + c) * DIM))[k4];
    }

    const int f_cg = tid >> 4, f_bb = (tid >> 2) & 3, f_c = tid & 3;
    const int f_col = col0 + f_cg * 4 + f_c;

    int pbb[4], pk4[4];
#pragma unroll
    for (int j = 0; j < 4; ++j) {
        int idx = tid + j * 256;
        pbb[j] = idx >> 8;
        pk4[j] = idx & 255;
    }

    __syncthreads();

    for (int t = 0; t < SEQ; ++t) {
        float pval = 0.f, gval = 0.f;
        if (tid < 32) {
            pval = P[((size_t)f_bb * SEQ + t) * DIM + f_col];
            if (t + 1 < SEQ)
                gval = gate[((size_t)f_bb * SEQ + (t + 1)) * DIM + f_col];
        }

        if (t > 0 && warp == 0) {
            unsigned tgt = (unsigned)t;
            bool ok;
            do {
                bool good = true;
#pragma unroll
                for (int j = 0; j < 4; ++j) {
                    unsigned f = *(volatile const unsigned*)
                        &g_flags[(lane + 32 * j) * FLAG_STRIDE];
                    good = good && (f >= tgt);
                }
                ok = __all_sync(0xffffffffu, good);
            } while (!ok);
        }
        __syncthreads();

        if (t == 0) {
#pragma unroll
            for (int j = 0; j < 4; ++j)
                ((float4*)(xs + pbb[j] * DIM))[pk4[j]] = make_float4(0.f, 0.f, 0.f, 0.f);
        } else {
#pragma unroll
            for (int j = 0; j < 4; ++j) {
                float4 y4 = __ldcg(&((const float4*)(g_y + ((size_t)pbb[j] * SEQ + t - 1) * DIM))[pk4[j]]);
                ((float4*)(xs + pbb[j] * DIM))[pk4[j]] = y4;
            }
        }
        __syncthreads();

        float acc[4][4];
#pragma unroll
        for (int bb = 0; bb < 4; ++bb)
#pragma unroll
            for (int c = 0; c < 4; ++c) acc[bb][c] = 0.f;

#pragma unroll
        for (int i = 0; i < 2; ++i) {
            int k4 = ks * 64 + i * 32 + lane;
            float4 x4[4];
#pragma unroll
            for (int bb = 0; bb < 4; ++bb)
                x4[bb] = ((const float4*)(xs + bb * DIM))[k4];
#pragma unroll
            for (int c = 0; c < 4; ++c) {
                float4 a4 = ((const float4*)(Asub + (cg * 4 + c) * DIM))[k4];
#pragma unroll
                for (int bb = 0; bb < 4; ++bb) {
                    acc[bb][c] += x4[bb].x * a4.x + x4[bb].y * a4.y +
                                  x4[bb].z * a4.z + x4[bb].w * a4.w;
                }
            }
        }
#pragma unroll
        for (int bb = 0; bb < 4; ++bb)
#pragma unroll
            for (int c = 0; c < 4; ++c) {
                float v = acc[bb][c];
#pragma unroll
                for (int off = 16; off; off >>= 1)
                    v += __shfl_xor_sync(0xffffffffu, v, off);
                acc[bb][c] = v;
            }
        if (lane == 0) {
#pragma unroll
            for (int bb = 0; bb < 4; ++bb)
#pragma unroll
                for (int c = 0; c < 4; ++c)
                    red[warp * 16 + bb * 4 + c] = acc[bb][c];
        }
        __syncthreads();

        if (tid < 32) {
            float s = 0.f;
#pragma unroll
            for (int k = 0; k < 4; ++k)
                s += red[(k * 2 + f_cg) * 16 + f_bb * 4 + f_c];
            float sv = tanhf(s + pval);
            size_t idx = ((size_t)f_bb * SEQ + t) * DIM + f_col;
            // publish hi/lo bf16 split of state (bit-identical to in-GEMM split)
            uint32_t usv = __float_as_uint(sv);
            unsigned short h = (unsigned short)(usv >> 16);
            float res = sv - __uint_as_float(usv & 0xFFFF0000u);
            unsigned short lb = __bfloat16_as_ushort(__float2bfloat16(res));
            asm volatile("st.global.cg.u16 [%0], %1;" :: "l"((uint16_t*)&stHi[idx]), "h"(h) : "memory");
            asm volatile("st.global.cg.u16 [%0], %1;" :: "l"((uint16_t*)&stLo[idx]), "h"(lb) : "memory");
            if (t + 1 < SEQ)
                __stcg(&g_y[idx], sv * gval);
            __threadfence();
        }
        __syncthreads();

        if (tid == 0)
            *(volatile unsigned*)&g_flags[blockIdx.x * FLAG_STRIDE] = (unsigned)(t + 1);
        __syncthreads();
    }
}

__global__ void reset_flags()
{
    int i = threadIdx.x;
    if (i < REC_CTAS * FLAG_STRIDE) g_flags[i] = 0u;
}

// ================= launch =================
extern "C" void kernel_launch(void* const* d_in, const int* in_sizes, int n_in,
                              void* d_out, int out_size)
{
    const float* q     = (const float*)d_in[0];
    const float* k     = (const float*)d_in[1];
    const float* v     = (const float*)d_in[2];
    const float* Wi    = (const float*)d_in[3];
    const float* bi    = (const float*)d_in[4];
    const float* Wg    = (const float*)d_in[5];
    const float* bg    = (const float*)d_in[6];
    const float* A     = (const float*)d_in[7];
    const float* Bm    = (const float*)d_in[8];
    const float* Wo    = (const float*)d_in[9];
    const float* bo    = (const float*)d_in[10];
    const float* decay = (const float*)d_in[11];

    float *inp, *gate, *p;
    cudaGetSymbolAddress((void**)&inp,  g_inp);
    cudaGetSymbolAddress((void**)&gate, g_gate);
    cudaGetSymbolAddress((void**)&p,    g_p);

    __nv_bfloat16 *rethi, *retlo, *inphi, *inplo, *uhi, *ulo, *sthi, *stlo, *whi, *wlo;
    cudaGetSymbolAddress((void**)&rethi, g_rethi);
    cudaGetSymbolAddress((void**)&retlo, g_retlo);
    cudaGetSymbolAddress((void**)&inphi, g_inphi);
    cudaGetSymbolAddress((void**)&inplo, g_inplo);
    cudaGetSymbolAddress((void**)&uhi,   g_uhi);
    cudaGetSymbolAddress((void**)&ulo,   g_ulo);
    cudaGetSymbolAddress((void**)&sthi,  g_sthi);
    cudaGetSymbolAddress((void**)&stlo,  g_stlo);
    cudaGetSymbolAddress((void**)&whi,   g_whi);
    cudaGetSymbolAddress((void**)&wlo,   g_wlo);
    const size_t WSZ = (size_t)DIM * DIM;

    cudaFuncSetAttribute(recurrence_kernel,
                         cudaFuncAttributeMaxDynamicSharedMemorySize, REC_SMEM);
    cudaFuncSetAttribute(mma_gemm,
                         cudaFuncAttributeMaxDynamicSharedMemorySize, GM_SMEM);

    // weight pre-conversion
    const int cgn = (DIM * DIM / 4) / 256;   // 1024 blocks
    cvt_w<<<cgn, 256>>>(Wi, whi + 0 * WSZ, wlo + 0 * WSZ);
    cvt_w<<<cgn, 256>>>(Wg, whi + 1 * WSZ, wlo + 1 * WSZ);
    cvt_w<<<cgn, 256>>>(A,  whi + 2 * WSZ, wlo + 2 * WSZ);
    cvt_w<<<cgn, 256>>>(Bm, whi + 3 * WSZ, wlo + 3 * WSZ);
    cvt_w<<<cgn, 256>>>(Wo, whi + 4 * WSZ, wlo + 4 * WSZ);

    dim3 sg(DIM / 256, NCHUNK, BATCH);
    scan_pass1<<<sg, 256>>>(k, v, decay);
    scan_pass2<<<dim3(DIM / 256, BATCH), 256>>>(decay);
    scan_pass3<<<sg, 256>>>(q, k, v, decay);

    dim3 gg(DIM / 128, MROWS / 128);   // (8, 64)
    // inp = ret @ Wi^T + bi   (emit fp32 + hi/lo)
    mma_gemm<<<gg, 256, GM_SMEM>>>(rethi, retlo, whi + 0 * WSZ, wlo + 0 * WSZ,
                                   nullptr, nullptr, nullptr, nullptr,
                                   bi, inp, inphi, inplo,
                                   nullptr, nullptr, nullptr, 0, 0);
    // gate = sigmoid(inp @ Wg^T + bg);  u = (1-gate)*inp  (emit u hi/lo)
    mma_gemm<<<gg, 256, GM_SMEM>>>(inphi, inplo, whi + 1 * WSZ, wlo + 1 * WSZ,
                                   nullptr, nullptr, nullptr, nullptr,
                                   bg, gate, nullptr, nullptr,
                                   inp, uhi, ulo, 1, 0);
    // p = u @ A^T + inp @ Bm^T   (fused dual accumulation)
    mma_gemm<<<gg, 256, GM_SMEM>>>(uhi, ulo, whi + 2 * WSZ, wlo + 2 * WSZ,
                                   inphi, inplo, whi + 3 * WSZ, wlo + 3 * WSZ,
                                   nullptr, p, nullptr, nullptr,
                                   nullptr, nullptr, nullptr, 3, 1);

    reset_flags<<<1, 1024>>>();
    recurrence_kernel<<<REC_CTAS, 256, REC_SMEM>>>(gate, p, A, sthi, stlo);

    // out = state @ Wo^T + bo
    mma_gemm<<<gg, 256, GM_SMEM>>>(sthi, stlo, whi + 4 * WSZ, wlo + 4 * WSZ,
                                   nullptr, nullptr, nullptr, nullptr,
                                   bo, (float*)d_out, nullptr, nullptr,
                                   nullptr, nullptr, nullptr, 0, 0);
}

// round 14
// speedup vs baseline: 1.8546x; 1.0310x over previous
#include <cuda_runtime.h>
#include <cuda_bf16.h>
#include <math.h>
#include <stdint.h>

#define BATCH 4
#define SEQ   2048
#define DIM   1024
#define NCHUNK 16
#define CHUNK  128          // SEQ / NCHUNK
#define MROWS  (BATCH * SEQ)   // 8192

// ---------------- scratch (static device globals; no allocation) ----------------
__device__ float g_inp  [(size_t)MROWS * DIM];
__device__ float g_gate [(size_t)MROWS * DIM];
__device__ float g_p    [(size_t)MROWS * DIM];
__device__ float g_y    [(size_t)MROWS * DIM];   // y_t = gate_{t+1} * state_t

// bf16 hi/lo operand chain (split is bit-identical to the old in-GEMM split)
__device__ __nv_bfloat16 g_rethi[(size_t)MROWS * DIM];
__device__ __nv_bfloat16 g_retlo[(size_t)MROWS * DIM];
__device__ __nv_bfloat16 g_inphi[(size_t)MROWS * DIM];
__device__ __nv_bfloat16 g_inplo[(size_t)MROWS * DIM];
__device__ __nv_bfloat16 g_uhi  [(size_t)MROWS * DIM];
__device__ __nv_bfloat16 g_ulo  [(size_t)MROWS * DIM];
__device__ __nv_bfloat16 g_sthi [(size_t)MROWS * DIM];
__device__ __nv_bfloat16 g_stlo [(size_t)MROWS * DIM];

// pre-converted bf16 weight splits: slots 0=Wi 1=Wg 2=A 3=Bm 4=Wo
__device__ __nv_bfloat16 g_whi[5][(size_t)DIM * DIM];
__device__ __nv_bfloat16 g_wlo[5][(size_t)DIM * DIM];

#define REC_CTAS 128
#define REC_COLS 8
#define FLAG_STRIDE 8
__device__ unsigned int g_flags[REC_CTAS * FLAG_STRIDE];

__device__ float g_E   [BATCH * NCHUNK * DIM];
__device__ float g_cin [BATCH * NCHUNK * DIM];

// ---------------- helpers ----------------
__device__ __forceinline__ uint32_t smem_u32(const void* p) {
    uint32_t a;
    asm("{ .reg .u64 t; cvta.to.shared.u64 t, %1; cvt.u32.u64 %0, t; }"
        : "=r"(a) : "l"(p));
    return a;
}
__device__ __forceinline__ void ldm4(uint32_t* r, uint32_t addr) {
    asm volatile("ldmatrix.sync.aligned.m8n8.x4.shared.b16 {%0,%1,%2,%3}, [%4];"
                 : "=r"(r[0]), "=r"(r[1]), "=r"(r[2]), "=r"(r[3]) : "r"(addr));
}
__device__ __forceinline__ void mma16816(float* d, const uint32_t* a, const uint32_t* b) {
    asm volatile("mma.sync.aligned.m16n8k16.row.col.f32.bf16.bf16.f32 "
                 "{%0,%1,%2,%3}, {%4,%5,%6,%7}, {%8,%9}, {%0,%1,%2,%3};"
                 : "+f"(d[0]), "+f"(d[1]), "+f"(d[2]), "+f"(d[3])
                 : "r"(a[0]), "r"(a[1]), "r"(a[2]), "r"(a[3]),
                   "r"(b[0]), "r"(b[1]));
}
#define CP16(dst, src) \
    asm volatile("cp.async.ca.shared.global [%0], [%1], 16;" \
                 :: "r"(dst), "l"(src) : "memory")
#define CP_COMMIT()   asm volatile("cp.async.commit_group;" ::: "memory")
#define CP_WAIT_ALL() asm volatile("cp.async.wait_group 0;" ::: "memory")

// split two fp32 into packed bf16x2 hi (truncate) and lo (rn residual) —
// bit-identical to the original in-GEMM ld_cvt split.
__device__ __forceinline__ void split2(float a, float b, uint32_t& hi, uint32_t& lo) {
    uint32_t ua = __float_as_uint(a), ub = __float_as_uint(b);
    hi = (ua >> 16) | (ub & 0xFFFF0000u);
    float ra = a - __uint_as_float(ua & 0xFFFF0000u);
    float rb = b - __uint_as_float(ub & 0xFFFF0000u);
    asm("cvt.rn.satfinite.bf16x2.f32 %0, %1, %2;" : "=r"(lo) : "f"(rb), "f"(ra));
}

// ---------------- weight pre-conversion: all 5 weights in ONE launch ----------------
__global__ void cvt_all(const float* __restrict__ W0, const float* __restrict__ W1,
                        const float* __restrict__ W2, const float* __restrict__ W3,
                        const float* __restrict__ W4)
{
    const float* Ws[5] = { W0, W1, W2, W3, W4 };
    const int s = blockIdx.y;
    const float* W = Ws[s];
    __nv_bfloat16* hi = g_whi[s];
    __nv_bfloat16* lo = g_wlo[s];
    int i = blockIdx.x * 256 + threadIdx.x;          // float4 index, 262144 total
    float4 v = ((const float4*)W)[i];
    uint2 h, l;
    split2(v.x, v.y, h.x, l.x);
    split2(v.z, v.w, h.y, l.y);
    ((uint2*)hi)[i] = h;
    ((uint2*)lo)[i] = l;
}

// ---------------- retention scan ----------------
__global__ void scan_pass1(const float* __restrict__ K, const float* __restrict__ V,
                           const float* __restrict__ decay)
{
    int d = blockIdx.x * 256 + threadIdx.x;
    int c = blockIdx.y;
    int b = blockIdx.z;
    float dec = decay[d >> 6];
    size_t base = ((size_t)b * SEQ + (size_t)c * CHUNK) * DIM + d;
    const float* kp = K + base;
    const float* vp = V + base;
    float r = 0.f;
#pragma unroll 8
    for (int i = 0; i < CHUNK; ++i)
        r = dec * r + kp[(size_t)i * DIM] * vp[(size_t)i * DIM];
    g_E[((size_t)b * NCHUNK + c) * DIM + d] = r;
}

__global__ void scan_pass2(const float* __restrict__ decay)
{
    int d = blockIdx.x * 256 + threadIdx.x;
    int b = blockIdx.y;
    float dec = decay[d >> 6];
    float decC = 1.f;
#pragma unroll
    for (int i = 0; i < CHUNK; ++i) decC *= dec;
    float carry = 0.f;
#pragma unroll
    for (int c = 0; c < NCHUNK; ++c) {
        size_t idx = ((size_t)b * NCHUNK + c) * DIM + d;
        g_cin[idx] = carry;
        carry = carry * decC + g_E[idx];
    }
}

__global__ void scan_pass3(const float* __restrict__ Q, const float* __restrict__ K,
                           const float* __restrict__ V, const float* __restrict__ decay)
{
    int d = blockIdx.x * 256 + threadIdx.x;
    int c = blockIdx.y;
    int b = blockIdx.z;
    float dec = decay[d >> 6];
    size_t base = ((size_t)b * SEQ + (size_t)c * CHUNK) * DIM + d;
    const float* qp = Q + base;
    const float* kp = K + base;
    const float* vp = V + base;
    float r = g_cin[((size_t)b * NCHUNK + c) * DIM + d];
#pragma unroll 8
    for (int i = 0; i < CHUNK; ++i) {
        r = dec * r + kp[(size_t)i * DIM] * vp[(size_t)i * DIM];
        float ret = qp[(size_t)i * DIM] * r;
        uint32_t u = __float_as_uint(ret);
        size_t idx = base + (size_t)i * DIM;
        *(uint16_t*)&g_rethi[idx] = (uint16_t)(u >> 16);
        float res = ret - __uint_as_float(u & 0xFFFF0000u);
        g_retlo[idx] = __float2bfloat16(res);
    }
}

// ================= cp.async pipelined bf16-native split GEMM =================
// C[m,n] = sum_k X[m,k]*W[n,k] (+ optional X2,W2 accumulated)
// D = Xhi*Whi + Xhi*Wlo + Xlo*Whi, fp32 register accumulators.
// ALL operands pre-split bf16 in gmem -> pure cp.async 16B copies, no cvt/STS.
// Tile 128x128/CTA, BK=32, 8 warps (4m x 2n), double-buffered, 1 barrier/chunk.
#define GM_LDS    40                        // padded row elements: 80B stride
#define GM_TILE_B (128 * GM_LDS * 2)        // 10240 B per (tile,part)
#define GM_BUF_B  (4 * GM_TILE_B)           // Ahi|Alo|Bhi|Blo = 40960 B
#define GM_SMEM   (2 * GM_BUF_B)            // 81920 B

__device__ __forceinline__ void cp_tile(uint32_t sHi, uint32_t sLo,
                                        const __nv_bfloat16* __restrict__ hi,
                                        const __nv_bfloat16* __restrict__ lo,
                                        int rowBase, int kBase, int tid)
{
    const int row = tid >> 1;
    const int cb  = (tid & 1) * 16;
    const __nv_bfloat16* gh = hi + (size_t)(rowBase + row) * DIM + kBase + cb;
    const __nv_bfloat16* gl = lo + (size_t)(rowBase + row) * DIM + kBase + cb;
    const uint32_t so = 2u * (row * GM_LDS + cb);
    CP16(sHi + so,      gh);
    CP16(sHi + so + 16, gh + 8);
    CP16(sLo + so,      gl);
    CP16(sLo + so + 16, gl + 8);
}

__global__ __launch_bounds__(256)
void mma_gemm(const __nv_bfloat16* __restrict__ X1hi, const __nv_bfloat16* __restrict__ X1lo,
              const __nv_bfloat16* __restrict__ W1hi, const __nv_bfloat16* __restrict__ W1lo,
              const __nv_bfloat16* __restrict__ X2hi, const __nv_bfloat16* __restrict__ X2lo,
              const __nv_bfloat16* __restrict__ W2hi, const __nv_bfloat16* __restrict__ W2lo,
              const float* __restrict__ bias, float* __restrict__ C,
              __nv_bfloat16* __restrict__ Chi, __nv_bfloat16* __restrict__ Clo,
              const float* __restrict__ auxIn,
              __nv_bfloat16* __restrict__ uHi, __nv_bfloat16* __restrict__ uLo,
              int mode, int dual)
{
    extern __shared__ char dyn[];
    const uint32_t sb = smem_u32(dyn);
    const int tid = threadIdx.x;
    const int wid = tid >> 5, lane = tid & 31;
    const int wm = wid >> 1;
    const int wn = wid & 1;
    const int nTile = blockIdx.x * 128;
    const int mTile = blockIdx.y * 128;

    float acc[2][8][4];
#pragma unroll
    for (int mt = 0; mt < 2; ++mt)
#pragma unroll
        for (int nt = 0; nt < 8; ++nt)
#pragma unroll
            for (int r = 0; r < 4; ++r) acc[mt][nt][r] = 0.f;

    const uint32_t aRow  = wm * 32 + (lane & 15);
    const uint32_t aKoff = (lane >> 4) * 8;
    const uint32_t bRow  = wn * 64 + (lane & 7) + ((lane >> 4) << 3);
    const uint32_t bKoff = ((lane >> 3) & 1) * 8;

    // prologue: chunk 0 -> buf0
    cp_tile(sb, sb + GM_TILE_B, X1hi, X1lo, mTile, 0, tid);
    cp_tile(sb + 2 * GM_TILE_B, sb + 3 * GM_TILE_B, W1hi, W1lo, nTile, 0, tid);
    CP_COMMIT();
    CP_WAIT_ALL();
    __syncthreads();

    const int nCh = dual ? 64 : 32;
    for (int c = 0; c < nCh; ++c) {
        const int buf = c & 1;

        // async prefetch of chunk c+1 into the other buffer
        if (c + 1 < nCh) {
            const int c1 = c + 1;
            const __nv_bfloat16* Xh = (c1 >= 32) ? X2hi : X1hi;
            const __nv_bfloat16* Xl = (c1 >= 32) ? X2lo : X1lo;
            const __nv_bfloat16* Wh = (c1 >= 32) ? W2hi : W1hi;
            const __nv_bfloat16* Wl = (c1 >= 32) ? W2lo : W1lo;
            const int kB = (c1 & 31) * 32;
            const uint32_t nb = sb + (buf ^ 1) * GM_BUF_B;
            cp_tile(nb, nb + GM_TILE_B, Xh, Xl, mTile, kB, tid);
            cp_tile(nb + 2 * GM_TILE_B, nb + 3 * GM_TILE_B, Wh, Wl, nTile, kB, tid);
            CP_COMMIT();
        }

        // MMA on current buffer
        const uint32_t base = sb + buf * GM_BUF_B;
#pragma unroll
        for (int kk = 0; kk < 2; ++kk) {
            uint32_t ahi[2][4], alo[2][4];
#pragma unroll
            for (int mt = 0; mt < 2; ++mt) {
                uint32_t off = 2u * ((aRow + mt * 16) * GM_LDS + kk * 16 + aKoff);
                ldm4(ahi[mt], base + off);
                ldm4(alo[mt], base + GM_TILE_B + off);
            }
#pragma unroll
            for (int ng = 0; ng < 4; ++ng) {
                uint32_t bhi[4], blo[4];
                uint32_t off = 2u * ((bRow + ng * 16) * GM_LDS + kk * 16 + bKoff);
                ldm4(bhi, base + 2 * GM_TILE_B + off);
                ldm4(blo, base + 3 * GM_TILE_B + off);
#pragma unroll
                for (int mt = 0; mt < 2; ++mt)
#pragma unroll
                    for (int h = 0; h < 2; ++h) {
                        float* d = acc[mt][ng * 2 + h];
                        mma16816(d, ahi[mt], bhi + h * 2);
                        mma16816(d, ahi[mt], blo + h * 2);
                        mma16816(d, alo[mt], bhi + h * 2);
                    }
            }
        }
        if (c + 1 < nCh) CP_WAIT_ALL();
        __syncthreads();
    }

    // ---- epilogue from register accumulators ----
    const int g = lane >> 2, tig = lane & 3;
#pragma unroll
    for (int mt = 0; mt < 2; ++mt) {
#pragma unroll
        for (int nt = 0; nt < 8; ++nt) {
            const int col = nTile + wn * 64 + nt * 8 + tig * 2;
            const int r0 = mTile + wm * 32 + mt * 16 + g;
            const int r1 = r0 + 8;
            float* d = acc[mt][nt];
            if (mode == 0) {
                float2 bv = *(const float2*)(bias + col);
                float2 o0 = make_float2(d[0] + bv.x, d[1] + bv.y);
                float2 o1 = make_float2(d[2] + bv.x, d[3] + bv.y);
                *(float2*)(C + (size_t)r0 * DIM + col) = o0;
                *(float2*)(C + (size_t)r1 * DIM + col) = o1;
                if (Chi) {
                    uint32_t h0, l0, h1, l1;
                    split2(o0.x, o0.y, h0, l0);
                    split2(o1.x, o1.y, h1, l1);
                    *(uint32_t*)(Chi + (size_t)r0 * DIM + col) = h0;
                    *(uint32_t*)(Clo + (size_t)r0 * DIM + col) = l0;
                    *(uint32_t*)(Chi + (size_t)r1 * DIM + col) = h1;
                    *(uint32_t*)(Clo + (size_t)r1 * DIM + col) = l1;
                }
            } else if (mode == 1) {
                float2 bv = *(const float2*)(bias + col);
                float2 i0 = *(const float2*)(auxIn + (size_t)r0 * DIM + col);
                float2 i1 = *(const float2*)(auxIn + (size_t)r1 * DIM + col);
                float g0 = 1.f / (1.f + __expf(-(d[0] + bv.x)));
                float g1 = 1.f / (1.f + __expf(-(d[1] + bv.y)));
                float g2 = 1.f / (1.f + __expf(-(d[2] + bv.x)));
                float g3 = 1.f / (1.f + __expf(-(d[3] + bv.y)));
                *(float2*)(C + (size_t)r0 * DIM + col) = make_float2(g0, g1);
                *(float2*)(C + (size_t)r1 * DIM + col) = make_float2(g2, g3);
                float u0 = (1.f - g0) * i0.x, u1 = (1.f - g1) * i0.y;
                float u2 = (1.f - g2) * i1.x, u3 = (1.f - g3) * i1.y;
                uint32_t h0, l0, h1, l1;
                split2(u0, u1, h0, l0);
                split2(u2, u3, h1, l1);
                *(uint32_t*)(uHi + (size_t)r0 * DIM + col) = h0;
                *(uint32_t*)(uLo + (size_t)r0 * DIM + col) = l0;
                *(uint32_t*)(uHi + (size_t)r1 * DIM + col) = h1;
                *(uint32_t*)(uLo + (size_t)r1 * DIM + col) = l1;
            } else {
                *(float2*)(C + (size_t)r0 * DIM + col) = make_float2(d[0], d[1]);
                *(float2*)(C + (size_t)r1 * DIM + col) = make_float2(d[2], d[3]);
            }
        }
    }
}

// ================= persistent state recurrence (v5 — FROZEN; finisher emits bf16 split) =================
#define REC_SMEM ((REC_COLS * DIM + BATCH * DIM + 8 * 16) * 4)

__global__ __launch_bounds__(256, 1)
void recurrence_kernel(const float* __restrict__ gate, const float* __restrict__ P,
                       const float* __restrict__ Amat,
                       __nv_bfloat16* __restrict__ stHi, __nv_bfloat16* __restrict__ stLo)
{
    extern __shared__ float sh[];
    float* Asub = sh;
    float* xs   = sh + REC_COLS * DIM;
    float* red  = xs + BATCH * DIM;

    const int tid = threadIdx.x;
    const int warp = tid >> 5, lane = tid & 31;
    const int col0 = blockIdx.x * REC_COLS;
    const int cg = warp & 1;
    const int ks = warp >> 1;

    for (int i = tid; i < REC_COLS * DIM / 4; i += 256) {
        int c = i >> 8, k4 = i & 255;
        ((float4*)(Asub + c * DIM))[k4] =
            ((const float4*)(Amat + (size_t)(col0 + c) * DIM))[k4];
    }

    const int f_cg = tid >> 4, f_bb = (tid >> 2) & 3, f_c = tid & 3;
    const int f_col = col0 + f_cg * 4 + f_c;

    int pbb[4], pk4[4];
#pragma unroll
    for (int j = 0; j < 4; ++j) {
        int idx = tid + j * 256;
        pbb[j] = idx >> 8;
        pk4[j] = idx & 255;
    }

    __syncthreads();

    for (int t = 0; t < SEQ; ++t) {
        float pval = 0.f, gval = 0.f;
        if (tid < 32) {
            pval = P[((size_t)f_bb * SEQ + t) * DIM + f_col];
            if (t + 1 < SEQ)
                gval = gate[((size_t)f_bb * SEQ + (t + 1)) * DIM + f_col];
        }

        if (t > 0 && warp == 0) {
            unsigned tgt = (unsigned)t;
            bool ok;
            do {
                bool good = true;
#pragma unroll
                for (int j = 0; j < 4; ++j) {
                    unsigned f = *(volatile const unsigned*)
                        &g_flags[(lane + 32 * j) * FLAG_STRIDE];
                    good = good && (f >= tgt);
                }
                ok = __all_sync(0xffffffffu, good);
            } while (!ok);
        }
        __syncthreads();

        if (t == 0) {
#pragma unroll
            for (int j = 0; j < 4; ++j)
                ((float4*)(xs + pbb[j] * DIM))[pk4[j]] = make_float4(0.f, 0.f, 0.f, 0.f);
        } else {
#pragma unroll
            for (int j = 0; j < 4; ++j) {
                float4 y4 = __ldcg(&((const float4*)(g_y + ((size_t)pbb[j] * SEQ + t - 1) * DIM))[pk4[j]]);
                ((float4*)(xs + pbb[j] * DIM))[pk4[j]] = y4;
            }
        }
        __syncthreads();

        float acc[4][4];
#pragma unroll
        for (int bb = 0; bb < 4; ++bb)
#pragma unroll
            for (int c = 0; c < 4; ++c) acc[bb][c] = 0.f;

#pragma unroll
        for (int i = 0; i < 2; ++i) {
            int k4 = ks * 64 + i * 32 + lane;
            float4 x4[4];
#pragma unroll
            for (int bb = 0; bb < 4; ++bb)
                x4[bb] = ((const float4*)(xs + bb * DIM))[k4];
#pragma unroll
            for (int c = 0; c < 4; ++c) {
                float4 a4 = ((const float4*)(Asub + (cg * 4 + c) * DIM))[k4];
#pragma unroll
                for (int bb = 0; bb < 4; ++bb) {
                    acc[bb][c] += x4[bb].x * a4.x + x4[bb].y * a4.y +
                                  x4[bb].z * a4.z + x4[bb].w * a4.w;
                }
            }
        }
#pragma unroll
        for (int bb = 0; bb < 4; ++bb)
#pragma unroll
            for (int c = 0; c < 4; ++c) {
                float v = acc[bb][c];
#pragma unroll
                for (int off = 16; off; off >>= 1)
                    v += __shfl_xor_sync(0xffffffffu, v, off);
                acc[bb][c] = v;
            }
        if (lane == 0) {
#pragma unroll
            for (int bb = 0; bb < 4; ++bb)
#pragma unroll
                for (int c = 0; c < 4; ++c)
                    red[warp * 16 + bb * 4 + c] = acc[bb][c];
        }
        __syncthreads();

        if (tid < 32) {
            float s = 0.f;
#pragma unroll
            for (int k = 0; k < 4; ++k)
                s += red[(k * 2 + f_cg) * 16 + f_bb * 4 + f_c];
            float sv = tanhf(s + pval);
            size_t idx = ((size_t)f_bb * SEQ + t) * DIM + f_col;
            uint32_t usv = __float_as_uint(sv);
            unsigned short h = (unsigned short)(usv >> 16);
            float res = sv - __uint_as_float(usv & 0xFFFF0000u);
            unsigned short lb = __bfloat16_as_ushort(__float2bfloat16(res));
            asm volatile("st.global.cg.u16 [%0], %1;" :: "l"((uint16_t*)&stHi[idx]), "h"(h) : "memory");
            asm volatile("st.global.cg.u16 [%0], %1;" :: "l"((uint16_t*)&stLo[idx]), "h"(lb) : "memory");
            if (t + 1 < SEQ)
                __stcg(&g_y[idx], sv * gval);
            __threadfence();
        }
        __syncthreads();

        if (tid == 0)
            *(volatile unsigned*)&g_flags[blockIdx.x * FLAG_STRIDE] = (unsigned)(t + 1);
        __syncthreads();
    }
}

__global__ void reset_flags()
{
    int i = threadIdx.x;
    if (i < REC_CTAS * FLAG_STRIDE) g_flags[i] = 0u;
}

// ================= launch =================
extern "C" void kernel_launch(void* const* d_in, const int* in_sizes, int n_in,
                              void* d_out, int out_size)
{
    const float* q     = (const float*)d_in[0];
    const float* k     = (const float*)d_in[1];
    const float* v     = (const float*)d_in[2];
    const float* Wi    = (const float*)d_in[3];
    const float* bi    = (const float*)d_in[4];
    const float* Wg    = (const float*)d_in[5];
    const float* bg    = (const float*)d_in[6];
    const float* A     = (const float*)d_in[7];
    const float* Bm    = (const float*)d_in[8];
    const float* Wo    = (const float*)d_in[9];
    const float* bo    = (const float*)d_in[10];
    const float* decay = (const float*)d_in[11];

    float *inp, *gate, *p;
    cudaGetSymbolAddress((void**)&inp,  g_inp);
    cudaGetSymbolAddress((void**)&gate, g_gate);
    cudaGetSymbolAddress((void**)&p,    g_p);

    __nv_bfloat16 *rethi, *retlo, *inphi, *inplo, *uhi, *ulo, *sthi, *stlo, *whi, *wlo;
    cudaGetSymbolAddress((void**)&rethi, g_rethi);
    cudaGetSymbolAddress((void**)&retlo, g_retlo);
    cudaGetSymbolAddress((void**)&inphi, g_inphi);
    cudaGetSymbolAddress((void**)&inplo, g_inplo);
    cudaGetSymbolAddress((void**)&uhi,   g_uhi);
    cudaGetSymbolAddress((void**)&ulo,   g_ulo);
    cudaGetSymbolAddress((void**)&sthi,  g_sthi);
    cudaGetSymbolAddress((void**)&stlo,  g_stlo);
    cudaGetSymbolAddress((void**)&whi,   g_whi);
    cudaGetSymbolAddress((void**)&wlo,   g_wlo);
    const size_t WSZ = (size_t)DIM * DIM;

    cudaFuncSetAttribute(recurrence_kernel,
                         cudaFuncAttributeMaxDynamicSharedMemorySize, REC_SMEM);
    cudaFuncSetAttribute(mma_gemm,
                         cudaFuncAttributeMaxDynamicSharedMemorySize, GM_SMEM);

    // weight pre-conversion: single launch, all 5 weights
    cvt_all<<<dim3((DIM * DIM / 4) / 256, 5), 256>>>(Wi, Wg, A, Bm, Wo);

    dim3 sg(DIM / 256, NCHUNK, BATCH);
    scan_pass1<<<sg, 256>>>(k, v, decay);
    scan_pass2<<<dim3(DIM / 256, BATCH), 256>>>(decay);
    scan_pass3<<<sg, 256>>>(q, k, v, decay);

    dim3 gg(DIM / 128, MROWS / 128);   // (8, 64)
    // inp = ret @ Wi^T + bi   (emit fp32 + hi/lo)
    mma_gemm<<<gg, 256, GM_SMEM>>>(rethi, retlo, whi + 0 * WSZ, wlo + 0 * WSZ,
                                   nullptr, nullptr, nullptr, nullptr,
                                   bi, inp, inphi, inplo,
                                   nullptr, nullptr, nullptr, 0, 0);
    // gate = sigmoid(inp @ Wg^T + bg);  u = (1-gate)*inp  (emit u hi/lo)
    mma_gemm<<<gg, 256, GM_SMEM>>>(inphi, inplo, whi + 1 * WSZ, wlo + 1 * WSZ,
                                   nullptr, nullptr, nullptr, nullptr,
                                   bg, gate, nullptr, nullptr,
                                   inp, uhi, ulo, 1, 0);
    // p = u @ A^T + inp @ Bm^T   (fused dual accumulation)
    mma_gemm<<<gg, 256, GM_SMEM>>>(uhi, ulo, whi + 2 * WSZ, wlo + 2 * WSZ,
                                   inphi, inplo, whi + 3 * WSZ, wlo + 3 * WSZ,
                                   nullptr, p, nullptr, nullptr,
                                   nullptr, nullptr, nullptr, 3, 1);

    reset_flags<<<1, 1024>>>();
    recurrence_kernel<<<REC_CTAS, 256, REC_SMEM>>>(gate, p, A, sthi, stlo);

    // out = state @ Wo^T + bo
    mma_gemm<<<gg, 256, GM_SMEM>>>(sthi, stlo, whi + 4 * WSZ, wlo + 4 * WSZ,
                                   nullptr, nullptr, nullptr, nullptr,
                                   bo, (float*)d_out, nullptr, nullptr,
                                   nullptr, nullptr, nullptr, 0, 0);
}